// round 2
// baseline (speedup 1.0000x reference)
#include <cuda_runtime.h>
#include <math.h>

#define NN 20000
#define EE 640000
#define AAT 64
#define FF 32

// ---------------- scratch (device globals; no allocation allowed) ----------
__device__ float g_ef[EE * 8];        // edge radial features (E,8)
__device__ float g_Y[EE * 3];         // sqrt(3)*unit vectors (E,3)
__device__ float g_s[NN * 32];        // scalar features (N,F)
__device__ float g_v[NN * 96];        // vector features, layout [n][c*32+f]
__device__ float g_aggs[NN * 32];
__device__ float g_aggv[NN * 96];     // layout [n][c*32+f]

// ---------------- edge geometry (layer independent, computed once) ---------
__global__ void geom_kernel(const float* __restrict__ coords,
                            const int* __restrict__ eidx) {
    int e = blockIdx.x * blockDim.x + threadIdx.x;
    if (e >= EE) return;
    int snd = eidx[e];
    int rcv = eidx[EE + e];
    float dx = coords[snd * 3 + 0] - coords[rcv * 3 + 0];
    float dy = coords[snd * 3 + 1] - coords[rcv * 3 + 1];
    float dz = coords[snd * 3 + 2] - coords[rcv * 3 + 2];
    float r = sqrtf(dx * dx + dy * dy + dz * dz + 1e-12f);
    float invr = 1.0f / r;
    float x = r * 0.2f;                       // r / RMAX
    float x3 = x * x * x;
    float x6 = x3 * x3;
    float x7 = x6 * x;
    float x8 = x7 * x;
    float fc = (x < 1.0f) ? (1.0f - 28.0f * x6 + 48.0f * x7 - 21.0f * x8) : 0.0f;
    const float kf = 0.6324555320336759f;     // sqrt(2/RMAX)
    float c = kf * invr * fc;
#pragma unroll
    for (int i = 0; i < 8; i++) {
        float npi = (float)(i + 1) * 3.14159265358979323846f;
        g_ef[e * 8 + i] = c * sinf(npi * x);
    }
    float sc = 1.7320508075688772f * invr;    // sqrt(3)/r
    g_Y[e * 3 + 0] = sc * dx;
    g_Y[e * 3 + 1] = sc * dy;
    g_Y[e * 3 + 2] = sc * dz;
}

// ---------------- node embedding: s = attrs @ embW --------------------------
__global__ void emb_kernel(const float* __restrict__ attrs,
                           const float* __restrict__ W) {
    int gid = blockIdx.x * 256 + threadIdx.x;   // < NN*32 exactly
    int n = gid >> 5;
    int f = gid & 31;
    float acc = 0.0f;
#pragma unroll 8
    for (int a = 0; a < 64; a++) acc += attrs[n * 64 + a] * W[a * 32 + f];
    g_s[gid] = acc;
}

// ---------------- fused edge kernel: radial MLP + message + scatter --------
// dynamic smem layout (floats): W1 512 | b1 64 | W2 10240 | EF 256 | Y 96 |
//                               H 2048 | Wout 5120 | idx 64 ints
#define EDGE_SMEM_BYTES ((512 + 64 + 10240 + 256 + 96 + 2048 + 5120) * 4 + 64 * 4)

__global__ __launch_bounds__(256) void edge_kernel(
    const int* __restrict__ eidx,
    const float* __restrict__ rW1, const float* __restrict__ rb1,
    const float* __restrict__ rW2, int hasV) {
    extern __shared__ float sm[];
    float* sW1 = sm;               // [8][64]
    float* sB1 = sW1 + 512;        // [64]
    float* sW2 = sB1 + 64;         // [64][160]
    float* sEF = sW2 + 10240;      // [32][8]
    float* sY  = sEF + 256;        // [32][3]
    float* sH  = sY + 96;          // [32][64]
    float* sWo = sH + 2048;        // [32][160]
    int*   sIdx = (int*)(sWo + 5120); // snd[32], rcv[32]

    int tid = threadIdx.x;
    int tx = tid & 31, ty = tid >> 5;

    for (int i = tid; i < 512; i += 256) sW1[i] = rW1[i];
    if (tid < 64) sB1[tid] = rb1[tid];
    for (int i = tid; i < 10240; i += 256) sW2[i] = rW2[i];

    const float INV = 0.17677669529663689f;   // 1/sqrt(32)

    for (int tile = blockIdx.x; tile < EE / 32; tile += gridDim.x) {
        __syncthreads();  // previous tile's message phase done
        int ebase = tile * 32;
        sEF[tid] = g_ef[ebase * 8 + tid];
        if (tid < 96) sY[tid] = g_Y[ebase * 3 + tid];
        if (tid >= 96 && tid < 128) sIdx[tid - 96] = eidx[ebase + tid - 96];
        if (tid >= 128 && tid < 160) sIdx[tid - 96] = eidx[EE + ebase + tid - 128];
        __syncthreads();

        // H = silu(EF @ W1 + b1):  32x64 outputs, 8 per thread
        for (int idx = tid; idx < 2048; idx += 256) {
            int e = idx >> 6, k = idx & 63;
            float acc = sB1[k];
#pragma unroll
            for (int i = 0; i < 8; i++) acc += sEF[e * 8 + i] * sW1[i * 64 + k];
            sH[idx] = acc / (1.0f + expf(-acc));
        }
        __syncthreads();

        // Wout = H @ W2:  32x160, thread tile = 4 edges x 5 outputs
        float acc[4][5];
#pragma unroll
        for (int j = 0; j < 4; j++)
#pragma unroll
            for (int p = 0; p < 5; p++) acc[j][p] = 0.0f;

#pragma unroll 4
        for (int k = 0; k < 64; k++) {
            float w2v[5];
#pragma unroll
            for (int p = 0; p < 5; p++) w2v[p] = sW2[k * 160 + p * 32 + tx];
#pragma unroll
            for (int j = 0; j < 4; j++) {
                float h = sH[(ty * 4 + j) * 64 + k];
#pragma unroll
                for (int p = 0; p < 5; p++) acc[j][p] += h * w2v[p];
            }
        }
#pragma unroll
        for (int j = 0; j < 4; j++)
#pragma unroll
            for (int p = 0; p < 5; p++)
                sWo[(ty * 4 + j) * 160 + p * 32 + tx] = acc[j][p];
        __syncthreads();

        // message + scatter: warp ty handles edges ty*4 .. ty*4+3, lane = feature
#pragma unroll
        for (int j = 0; j < 4; j++) {
            int e = ty * 4 + j;
            int snd = sIdx[e];
            int rcv = sIdx[32 + e];
            float y0 = sY[e * 3 + 0], y1 = sY[e * 3 + 1], y2 = sY[e * 3 + 2];
            float w0 = sWo[e * 160 + tx];
            float w1 = sWo[e * 160 + 32 + tx];
            float w2 = sWo[e * 160 + 64 + tx];
            float w3 = sWo[e * 160 + 96 + tx];
            float w4 = sWo[e * 160 + 128 + tx];
            float sj = g_s[snd * 32 + tx];
            float ms, mv0, mv1, mv2;
            if (hasV) {
                float vj0 = g_v[snd * 96 + tx];
                float vj1 = g_v[snd * 96 + 32 + tx];
                float vj2 = g_v[snd * 96 + 64 + tx];
                float dot = vj0 * y0 + vj1 * y1 + vj2 * y2;
                float cx = vj1 * y2 - vj2 * y1;
                float cy = vj2 * y0 - vj0 * y2;
                float cz = vj0 * y1 - vj1 * y0;
                ms  = (w0 * sj + w3 * dot) * INV;
                mv0 = (w1 * sj * y0 + w2 * vj0 + w4 * cx) * INV;
                mv1 = (w1 * sj * y1 + w2 * vj1 + w4 * cy) * INV;
                mv2 = (w1 * sj * y2 + w2 * vj2 + w4 * cz) * INV;
            } else {
                ms  = w0 * sj * INV;
                float t = w1 * sj * INV;
                mv0 = t * y0; mv1 = t * y1; mv2 = t * y2;
            }
            atomicAdd(&g_aggs[rcv * 32 + tx], ms);
            atomicAdd(&g_aggv[rcv * 96 + tx], mv0);
            atomicAdd(&g_aggv[rcv * 96 + 32 + tx], mv1);
            atomicAdd(&g_aggv[rcv * 96 + 64 + tx], mv2);
        }
    }
}

// ---------------- node update: lin + self-connection einsums + gating ------
// 32 nodes / block, thread tile = 4 nodes x 5 outputs (2x pre_s-half + 3x pre_v-c)
__global__ __launch_bounds__(256) void node_kernel(
    const float* __restrict__ attrs,
    const float* __restrict__ Ls, const float* __restrict__ Lv,
    const float* __restrict__ Ws, const float* __restrict__ Wv) {
    __shared__ float sS[32 * 32];
    __shared__ float sV[32 * 96];
    __shared__ float sAt[32 * 64];
    __shared__ float sAgS[32 * 32];
    __shared__ float sAgV[32 * 96];

    int tid = threadIdx.x;
    int tx = tid & 31, ty = tid >> 5;
    int base = blockIdx.x * 32;

    for (int i = tid; i < 1024; i += 256) sS[i] = g_s[base * 32 + i];
    for (int i = tid; i < 3072; i += 256) sV[i] = g_v[base * 96 + i];
    for (int i = tid; i < 2048; i += 256) sAt[i] = attrs[base * 64 + i];
    for (int i = tid; i < 1024; i += 256) sAgS[i] = g_aggs[base * 32 + i];
    for (int i = tid; i < 3072; i += 256) sAgV[i] = g_aggv[base * 96 + i];
    __syncthreads();

    float acc[4][5];
#pragma unroll
    for (int j = 0; j < 4; j++)
#pragma unroll
        for (int p = 0; p < 5; p++) acc[j][p] = 0.0f;

    for (int f = 0; f < 32; f++) {
        float sf[4], v0[4], v1[4], v2[4];
#pragma unroll
        for (int j = 0; j < 4; j++) {
            int n = ty * 4 + j;
            sf[j] = sS[n * 32 + f];
            v0[j] = sV[n * 96 + f];
            v1[j] = sV[n * 96 + 32 + f];
            v2[j] = sV[n * 96 + 64 + f];
        }
        {   // linear parts
            float Ls0 = Ls[f * 64 + tx];
            float Ls1 = Ls[f * 64 + 32 + tx];
            float Lv0 = Lv[f * 32 + tx];
#pragma unroll
            for (int j = 0; j < 4; j++) {
                int n = ty * 4 + j;
                float ag = sAgS[n * 32 + f];
                acc[j][0] += ag * Ls0;
                acc[j][1] += ag * Ls1;
                acc[j][2] += sAgV[n * 96 + f] * Lv0;
                acc[j][3] += sAgV[n * 96 + 32 + f] * Lv0;
                acc[j][4] += sAgV[n * 96 + 64 + f] * Lv0;
            }
        }
        const float* Wsf = Ws + f * 64 * 64;
        const float* Wvf = Wv + f * 64 * 32;
#pragma unroll 4
        for (int a = 0; a < 64; a++) {
            float W0  = Wsf[a * 64 + tx];
            float W1_ = Wsf[a * 64 + 32 + tx];
            float Wv0 = Wvf[a * 32 + tx];
#pragma unroll
            for (int j = 0; j < 4; j++) {
                int n = ty * 4 + j;
                float at = sAt[n * 64 + a];
                float us = sf[j] * at;
                float tv = at * Wv0;
                acc[j][0] += us * W0;
                acc[j][1] += us * W1_;
                acc[j][2] += v0[j] * tv;
                acc[j][3] += v1[j] * tv;
                acc[j][4] += v2[j] * tv;
            }
        }
    }

#pragma unroll
    for (int j = 0; j < 4; j++) {
        int n = ty * 4 + j;
        int gn = base + n;
        float ft = acc[j][0], gt = acc[j][1];
        float s_new = ft / (1.0f + expf(-ft)) + sS[n * 32 + tx];
        float sg = 1.0f / (1.0f + expf(-gt));
        g_s[gn * 32 + tx] = s_new;
        g_v[gn * 96 + tx]      = acc[j][2] * sg + sV[n * 96 + tx];
        g_v[gn * 96 + 32 + tx] = acc[j][3] * sg + sV[n * 96 + 32 + tx];
        g_v[gn * 96 + 64 + tx] = acc[j][4] * sg + sV[n * 96 + 64 + tx];
    }
}

// ---------------- output assembly: [s | v.reshape(N, F*3)] -----------------
__global__ void out_kernel(float* __restrict__ out) {
    int idx = blockIdx.x * 256 + threadIdx.x;
    if (idx >= NN * 128) return;
    int n = idx >> 7, j = idx & 127;
    float val;
    if (j < 32) {
        val = g_s[n * 32 + j];
    } else {
        int t = j - 32;
        int f = t / 3;
        int c = t - 3 * f;
        val = g_v[n * 96 + c * 32 + f];
    }
    out[idx] = val;
}

// ---------------- launch ---------------------------------------------------
extern "C" void kernel_launch(void* const* d_in, const int* in_sizes, int n_in,
                              void* d_out, int out_size) {
    const float* attrs  = (const float*)d_in[0];
    const float* coords = (const float*)d_in[1];
    const int*   eidx   = (const int*)d_in[2];
    const float* embW   = (const float*)d_in[3];
    const float* rW1    = (const float*)d_in[4];
    const float* rb1    = (const float*)d_in[5];
    const float* rW2    = (const float*)d_in[6];
    const float* Ls     = (const float*)d_in[7];
    const float* Lv     = (const float*)d_in[8];
    const float* Ws     = (const float*)d_in[9];
    const float* Wv     = (const float*)d_in[10];
    float* out = (float*)d_out;

    cudaFuncSetAttribute(edge_kernel,
                         cudaFuncAttributeMaxDynamicSharedMemorySize,
                         EDGE_SMEM_BYTES);

    void *pv = nullptr, *pas = nullptr, *pav = nullptr;
    cudaGetSymbolAddress(&pv, g_v);
    cudaGetSymbolAddress(&pas, g_aggs);
    cudaGetSymbolAddress(&pav, g_aggv);

    cudaMemsetAsync(pv, 0, NN * 96 * sizeof(float));
    geom_kernel<<<EE / 256, 256>>>(coords, eidx);
    emb_kernel<<<NN * 32 / 256, 256>>>(attrs, embW);

    for (int l = 0; l < 2; l++) {
        cudaMemsetAsync(pas, 0, NN * 32 * sizeof(float));
        cudaMemsetAsync(pav, 0, NN * 96 * sizeof(float));
        edge_kernel<<<888, 256, EDGE_SMEM_BYTES>>>(
            eidx, rW1 + l * 512, rb1 + l * 64, rW2 + l * 10240, l);
        node_kernel<<<625, 256>>>(
            attrs, Ls + l * 2048, Lv + l * 1024,
            Ws + l * 131072, Wv + l * 65536);
    }
    out_kernel<<<(NN * 128 + 255) / 256, 256>>>(out);
}

// round 3
// speedup vs baseline: 1.2673x; 1.2673x over previous
#include <cuda_runtime.h>
#include <math.h>

#define NN 20000
#define EE 640000

typedef unsigned long long ULL;

// ---------------- packed f32x2 helpers -------------------------------------
__device__ __forceinline__ ULL pk2(float lo, float hi) {
    ULL r; asm("mov.b64 %0,{%1,%2};" : "=l"(r) : "f"(lo), "f"(hi)); return r;
}
__device__ __forceinline__ ULL dup2(float v) { return pk2(v, v); }
__device__ __forceinline__ void upk2(ULL v, float& lo, float& hi) {
    asm("mov.b64 {%0,%1},%2;" : "=f"(lo), "=f"(hi) : "l"(v));
}
__device__ __forceinline__ void fma2(ULL& d, ULL a, ULL b) {
    asm("fma.rn.f32x2 %0,%1,%2,%0;" : "+l"(d) : "l"(a), "l"(b));
}
__device__ __forceinline__ ULL mul2(ULL a, ULL b) {
    ULL d; asm("mul.rn.f32x2 %0,%1,%2;" : "=l"(d) : "l"(a), "l"(b)); return d;
}

// ---------------- cp.async helpers ------------------------------------------
__device__ __forceinline__ void cpa16(void* smem_dst, const void* gsrc) {
    unsigned s = (unsigned)__cvta_generic_to_shared(smem_dst);
    asm volatile("cp.async.cg.shared.global [%0],[%1],16;" :: "r"(s), "l"(gsrc));
}
#define CP_COMMIT asm volatile("cp.async.commit_group;")

// ---------------- scratch ----------------------------------------------------
__device__ float g_ef[EE * 8];
__device__ float g_Y[EE * 3];
__device__ float g_s[NN * 32];
__device__ float g_v[NN * 96];     // [n][c*32+f]
__device__ float g_aggs[NN * 32];
__device__ float g_aggv[NN * 96];  // [n][c*32+f]

// ---------------- edge geometry ---------------------------------------------
__global__ void geom_kernel(const float* __restrict__ coords,
                            const int* __restrict__ eidx) {
    int e = blockIdx.x * blockDim.x + threadIdx.x;
    if (e >= EE) return;
    int snd = eidx[e];
    int rcv = eidx[EE + e];
    float dx = coords[snd * 3 + 0] - coords[rcv * 3 + 0];
    float dy = coords[snd * 3 + 1] - coords[rcv * 3 + 1];
    float dz = coords[snd * 3 + 2] - coords[rcv * 3 + 2];
    float r = sqrtf(dx * dx + dy * dy + dz * dz + 1e-12f);
    float invr = 1.0f / r;
    float x = r * 0.2f;
    float x3 = x * x * x;
    float x6 = x3 * x3;
    float x7 = x6 * x;
    float x8 = x7 * x;
    float fc = (x < 1.0f) ? (1.0f - 28.0f * x6 + 48.0f * x7 - 21.0f * x8) : 0.0f;
    const float kf = 0.6324555320336759f;
    float c = kf * invr * fc;
    float s1, c1;
    sincosf(3.14159265358979323846f * x, &s1, &c1);
    float twoc = 2.0f * c1;
    float sp = 0.0f, sn = s1;
    g_ef[e * 8 + 0] = c * sn;
#pragma unroll
    for (int i = 1; i < 8; i++) {
        float nx = twoc * sn - sp;
        sp = sn; sn = nx;
        g_ef[e * 8 + i] = c * sn;
    }
    float sc = 1.7320508075688772f * invr;
    g_Y[e * 3 + 0] = sc * dx;
    g_Y[e * 3 + 1] = sc * dy;
    g_Y[e * 3 + 2] = sc * dz;
}

// ---------------- node embedding -------------------------------------------
__global__ void emb_kernel(const float* __restrict__ attrs,
                           const float* __restrict__ W) {
    int gid = blockIdx.x * 256 + threadIdx.x;
    int n = gid >> 5;
    int f = gid & 31;
    float acc = 0.0f;
#pragma unroll 8
    for (int a = 0; a < 64; a++) acc += attrs[n * 64 + a] * W[a * 32 + f];
    g_s[gid] = acc;
}

// ---------------- fused edge kernel -----------------------------------------
// smem floats: W1 512 | b1 64 | W2 10240 | EF 288(pad) | Y 96 | H 2048 | Wo 5120 | idx 64i
#define EDGE_SMEM_BYTES ((512 + 64 + 10240 + 288 + 96 + 2048 + 5120) * 4 + 64 * 4)

__global__ __launch_bounds__(256) void edge_kernel(
    const int* __restrict__ eidx,
    const float* __restrict__ rW1, const float* __restrict__ rb1,
    const float* __restrict__ rW2, int hasV) {
    extern __shared__ float sm[];
    float* sW1 = sm;               // [8][64]
    float* sB1 = sW1 + 512;        // [64]
    float* sW2 = sB1 + 64;         // [64][160]
    float* sEF = sW2 + 10240;      // [32][9] padded
    float* sY  = sEF + 288;        // [32][3]
    float* sH  = sY + 96;          // [64][32]  (k-major, transposed)
    float* sWo = sH + 2048;        // [32][160]
    int*   sIdx = (int*)(sWo + 5120);

    int tid = threadIdx.x;
    int tx = tid & 31, ty = tid >> 5;
    int nA = ty * 4;

    for (int i = tid; i < 512; i += 256) sW1[i] = rW1[i];
    if (tid < 64) sB1[tid] = rb1[tid];
    for (int i = tid; i < 10240; i += 256) sW2[i] = rW2[i];

    const float INV = 0.17677669529663689f;   // 1/sqrt(32)

    for (int tile = blockIdx.x; tile < EE / 32; tile += gridDim.x) {
        __syncthreads();
        int ebase = tile * 32;
        sEF[(tid >> 3) * 9 + (tid & 7)] = g_ef[ebase * 8 + tid];
        if (tid < 96) sY[tid] = g_Y[ebase * 3 + tid];
        if (tid >= 96 && tid < 128) sIdx[tid - 96] = eidx[ebase + tid - 96];
        if (tid >= 128 && tid < 160) sIdx[tid - 96] = eidx[EE + ebase + tid - 128];
        __syncthreads();

        // H^T = silu(EF @ W1 + b1): thread -> (k, e), conflict-free via padded EF
        for (int idx = tid; idx < 2048; idx += 256) {
            int k = idx >> 5, e = idx & 31;
            float acc = sB1[k];
#pragma unroll
            for (int i = 0; i < 8; i++) acc += sEF[e * 9 + i] * sW1[i * 64 + k];
            sH[k * 32 + e] = acc / (1.0f + expf(-acc));
        }
        __syncthreads();

        // Wout = H @ W2 : packed f32x2 over edge pairs
        {
            ULL acc[2][5];
#pragma unroll
            for (int P = 0; P < 2; P++)
#pragma unroll
                for (int p = 0; p < 5; p++) acc[P][p] = 0ULL;

#pragma unroll 4
            for (int k = 0; k < 64; k++) {
                ULL h0 = *(const ULL*)&sH[k * 32 + nA];
                ULL h1 = *(const ULL*)&sH[k * 32 + nA + 2];
#pragma unroll
                for (int p = 0; p < 5; p++) {
                    ULL w2 = dup2(sW2[k * 160 + p * 32 + tx]);
                    fma2(acc[0][p], h0, w2);
                    fma2(acc[1][p], h1, w2);
                }
            }
#pragma unroll
            for (int P = 0; P < 2; P++)
#pragma unroll
                for (int p = 0; p < 5; p++) {
                    float lo, hi;
                    upk2(acc[P][p], lo, hi);
                    sWo[(nA + 2 * P) * 160 + p * 32 + tx] = lo;
                    sWo[(nA + 2 * P + 1) * 160 + p * 32 + tx] = hi;
                }
        }
        __syncthreads();

        // message + scatter: warp ty -> edges nA..nA+3, lane = feature
#pragma unroll
        for (int j = 0; j < 4; j++) {
            int e = nA + j;
            int snd = sIdx[e];
            int rcv = sIdx[32 + e];
            float y0 = sY[e * 3 + 0], y1 = sY[e * 3 + 1], y2 = sY[e * 3 + 2];
            float w0 = sWo[e * 160 + tx];
            float w1 = sWo[e * 160 + 32 + tx];
            float w2 = sWo[e * 160 + 64 + tx];
            float w3 = sWo[e * 160 + 96 + tx];
            float w4 = sWo[e * 160 + 128 + tx];
            float sj = g_s[snd * 32 + tx];
            float ms, mv0, mv1, mv2;
            if (hasV) {
                float vj0 = g_v[snd * 96 + tx];
                float vj1 = g_v[snd * 96 + 32 + tx];
                float vj2 = g_v[snd * 96 + 64 + tx];
                float dot = vj0 * y0 + vj1 * y1 + vj2 * y2;
                float cx = vj1 * y2 - vj2 * y1;
                float cy = vj2 * y0 - vj0 * y2;
                float cz = vj0 * y1 - vj1 * y0;
                ms  = (w0 * sj + w3 * dot) * INV;
                mv0 = (w1 * sj * y0 + w2 * vj0 + w4 * cx) * INV;
                mv1 = (w1 * sj * y1 + w2 * vj1 + w4 * cy) * INV;
                mv2 = (w1 * sj * y2 + w2 * vj2 + w4 * cz) * INV;
            } else {
                ms  = w0 * sj * INV;
                float t = w1 * sj * INV;
                mv0 = t * y0; mv1 = t * y1; mv2 = t * y2;
            }
            atomicAdd(&g_aggs[rcv * 32 + tx], ms);
            atomicAdd(&g_aggv[rcv * 96 + tx], mv0);
            atomicAdd(&g_aggv[rcv * 96 + 32 + tx], mv1);
            atomicAdd(&g_aggv[rcv * 96 + 64 + tx], mv2);
        }
    }
}

// ---------------- node update -----------------------------------------------
// smem floats: Wbuf 12288 (2x[Ws4096|Wv2048]) | Ls 2048 | Lv 1024 | AtT 2048 |
//              ST 1024 | VT 3072 | AgS 1024 | AgV 3072 = 25600 floats = 100KB
#define NODE_SMEM_BYTES (25600 * 4)

__global__ __launch_bounds__(256) void node_kernel(
    const float* __restrict__ attrs,
    const float* __restrict__ Ls, const float* __restrict__ Lv,
    const float* __restrict__ Ws, const float* __restrict__ Wv) {
    extern __shared__ float sm[];
    float* sWbuf = sm;             // 12288
    float* sLs  = sm + 12288;      // 2048
    float* sLv  = sLs + 2048;      // 1024
    float* sAtT = sLv + 1024;      // [a][n] 2048
    float* sST  = sAtT + 2048;     // [f][n] 1024
    float* sVT  = sST + 1024;      // [(c*32+f)][n] 3072
    float* sAgS = sVT + 3072;      // [f][n] 1024
    float* sAgV = sAgS + 1024;     // [(c*32+f)][n] 3072

    int tid = threadIdx.x, tx = tid & 31, ty = tid >> 5;
    int base = blockIdx.x * 32;
    int nA = ty * 4;

    // prefetch weight chunk for f=0
    {
        float4* d1 = (float4*)sWbuf;
        float4* d2 = (float4*)(sWbuf + 4096);
        const float4* s1 = (const float4*)Ws;
        const float4* s2 = (const float4*)Wv;
#pragma unroll
        for (int i = 0; i < 4; i++) cpa16(d1 + tid + i * 256, s1 + tid + i * 256);
#pragma unroll
        for (int i = 0; i < 2; i++) cpa16(d2 + tid + i * 256, s2 + tid + i * 256);
        CP_COMMIT;
    }

    for (int i = tid; i < 2048; i += 256) sLs[i] = Ls[i];
    for (int i = tid; i < 1024; i += 256) sLv[i] = Lv[i];
    for (int i = tid; i < 2048; i += 256)
        sAtT[i] = attrs[(base + (i & 31)) * 64 + (i >> 5)];
    for (int i = tid; i < 1024; i += 256)
        sST[i] = g_s[(base + (i & 31)) * 32 + (i >> 5)];
    for (int i = tid; i < 3072; i += 256)
        sVT[i] = g_v[(base + (i & 31)) * 96 + (i >> 5)];
    for (int i = tid; i < 1024; i += 256)
        sAgS[i] = g_aggs[(base + (i & 31)) * 32 + (i >> 5)];
    for (int i = tid; i < 3072; i += 256)
        sAgV[i] = g_aggv[(base + (i & 31)) * 96 + (i >> 5)];

    ULL acc0[2] = {0, 0}, acc1[2] = {0, 0}, acc2[2] = {0, 0},
        acc3[2] = {0, 0}, acc4[2] = {0, 0};

    for (int f = 0; f < 32; f++) {
        if (f < 31) {
            float* dst = sWbuf + ((f + 1) & 1) * 6144;
            float4* d1 = (float4*)dst;
            float4* d2 = (float4*)(dst + 4096);
            const float4* s1 = (const float4*)(Ws + (f + 1) * 4096);
            const float4* s2 = (const float4*)(Wv + (f + 1) * 2048);
#pragma unroll
            for (int i = 0; i < 4; i++) cpa16(d1 + tid + i * 256, s1 + tid + i * 256);
#pragma unroll
            for (int i = 0; i < 2; i++) cpa16(d2 + tid + i * 256, s2 + tid + i * 256);
            CP_COMMIT;
            asm volatile("cp.async.wait_group 1;");
        } else {
            asm volatile("cp.async.wait_group 0;");
        }
        __syncthreads();

        const float* sWs  = sWbuf + (f & 1) * 6144;
        const float* sWvv = sWs + 4096;

        float Ls0 = sLs[f * 64 + tx], Ls1 = sLs[f * 64 + 32 + tx], Lv0 = sLv[f * 32 + tx];
        ULL Ls02 = dup2(Ls0), Ls12 = dup2(Ls1), Lv02 = dup2(Lv0);

        ULL sf2[2], v02[2], v12[2], v22[2];
#pragma unroll
        for (int P = 0; P < 2; P++) {
            int nn = nA + 2 * P;
            sf2[P] = *(const ULL*)&sST[f * 32 + nn];
            v02[P] = *(const ULL*)&sVT[f * 32 + nn];
            v12[P] = *(const ULL*)&sVT[(32 + f) * 32 + nn];
            v22[P] = *(const ULL*)&sVT[(64 + f) * 32 + nn];
            ULL ag = *(const ULL*)&sAgS[f * 32 + nn];
            fma2(acc0[P], ag, Ls02);
            fma2(acc1[P], ag, Ls12);
            fma2(acc2[P], *(const ULL*)&sAgV[f * 32 + nn], Lv02);
            fma2(acc3[P], *(const ULL*)&sAgV[(32 + f) * 32 + nn], Lv02);
            fma2(acc4[P], *(const ULL*)&sAgV[(64 + f) * 32 + nn], Lv02);
        }

#pragma unroll 4
        for (int a = 0; a < 64; a++) {
            ULL at20 = *(const ULL*)&sAtT[a * 32 + nA];
            ULL at21 = *(const ULL*)&sAtT[a * 32 + nA + 2];
            ULL W02  = dup2(sWs[a * 64 + tx]);
            ULL W12  = dup2(sWs[a * 64 + 32 + tx]);
            ULL Wv02 = dup2(sWvv[a * 32 + tx]);
            {
                ULL us2 = mul2(sf2[0], at20);
                ULL tv2 = mul2(at20, Wv02);
                fma2(acc0[0], us2, W02);
                fma2(acc1[0], us2, W12);
                fma2(acc2[0], v02[0], tv2);
                fma2(acc3[0], v12[0], tv2);
                fma2(acc4[0], v22[0], tv2);
            }
            {
                ULL us2 = mul2(sf2[1], at21);
                ULL tv2 = mul2(at21, Wv02);
                fma2(acc0[1], us2, W02);
                fma2(acc1[1], us2, W12);
                fma2(acc2[1], v02[1], tv2);
                fma2(acc3[1], v12[1], tv2);
                fma2(acc4[1], v22[1], tv2);
            }
        }
        __syncthreads();
    }

    // epilogue
#pragma unroll
    for (int P = 0; P < 2; P++) {
        float ft[2], gt[2], a2[2], a3[2], a4[2];
        upk2(acc0[P], ft[0], ft[1]);
        upk2(acc1[P], gt[0], gt[1]);
        upk2(acc2[P], a2[0], a2[1]);
        upk2(acc3[P], a3[0], a3[1]);
        upk2(acc4[P], a4[0], a4[1]);
#pragma unroll
        for (int h = 0; h < 2; h++) {
            int gn = base + nA + 2 * P + h;
            float sg = 1.0f / (1.0f + expf(-gt[h]));
            g_s[gn * 32 + tx] = ft[h] / (1.0f + expf(-ft[h])) + g_s[gn * 32 + tx];
            g_v[gn * 96 + tx]      = a2[h] * sg + g_v[gn * 96 + tx];
            g_v[gn * 96 + 32 + tx] = a3[h] * sg + g_v[gn * 96 + 32 + tx];
            g_v[gn * 96 + 64 + tx] = a4[h] * sg + g_v[gn * 96 + 64 + tx];
        }
    }
}

// ---------------- output assembly -------------------------------------------
__global__ void out_kernel(float* __restrict__ out) {
    int idx = blockIdx.x * 256 + threadIdx.x;
    if (idx >= NN * 128) return;
    int n = idx >> 7, j = idx & 127;
    float val;
    if (j < 32) {
        val = g_s[n * 32 + j];
    } else {
        int t = j - 32;
        int f = t / 3;
        int c = t - 3 * f;
        val = g_v[n * 96 + c * 32 + f];
    }
    out[idx] = val;
}

// ---------------- launch -----------------------------------------------------
extern "C" void kernel_launch(void* const* d_in, const int* in_sizes, int n_in,
                              void* d_out, int out_size) {
    const float* attrs  = (const float*)d_in[0];
    const float* coords = (const float*)d_in[1];
    const int*   eidx   = (const int*)d_in[2];
    const float* embW   = (const float*)d_in[3];
    const float* rW1    = (const float*)d_in[4];
    const float* rb1    = (const float*)d_in[5];
    const float* rW2    = (const float*)d_in[6];
    const float* Ls     = (const float*)d_in[7];
    const float* Lv     = (const float*)d_in[8];
    const float* Ws     = (const float*)d_in[9];
    const float* Wv     = (const float*)d_in[10];
    float* out = (float*)d_out;

    cudaFuncSetAttribute(edge_kernel,
                         cudaFuncAttributeMaxDynamicSharedMemorySize,
                         EDGE_SMEM_BYTES);
    cudaFuncSetAttribute(node_kernel,
                         cudaFuncAttributeMaxDynamicSharedMemorySize,
                         NODE_SMEM_BYTES);

    void *pv = nullptr, *pas = nullptr, *pav = nullptr;
    cudaGetSymbolAddress(&pv, g_v);
    cudaGetSymbolAddress(&pas, g_aggs);
    cudaGetSymbolAddress(&pav, g_aggv);

    cudaMemsetAsync(pv, 0, NN * 96 * sizeof(float));
    geom_kernel<<<EE / 256, 256>>>(coords, eidx);
    emb_kernel<<<NN * 32 / 256, 256>>>(attrs, embW);

    for (int l = 0; l < 2; l++) {
        cudaMemsetAsync(pas, 0, NN * 32 * sizeof(float));
        cudaMemsetAsync(pav, 0, NN * 96 * sizeof(float));
        edge_kernel<<<888, 256, EDGE_SMEM_BYTES>>>(
            eidx, rW1 + l * 512, rb1 + l * 64, rW2 + l * 10240, l);
        node_kernel<<<625, 256, NODE_SMEM_BYTES>>>(
            attrs, Ls + l * 2048, Lv + l * 1024,
            Ws + l * 131072, Wv + l * 65536);
    }
    out_kernel<<<(NN * 128 + 255) / 256, 256>>>(out);
}

// round 4
// speedup vs baseline: 1.3701x; 1.0811x over previous
#include <cuda_runtime.h>
#include <math.h>

#define NN 20000
#define EE 640000

typedef unsigned long long ULL;

// ---------------- packed f32x2 helpers -------------------------------------
__device__ __forceinline__ ULL pk2(float lo, float hi) {
    ULL r; asm("mov.b64 %0,{%1,%2};" : "=l"(r) : "f"(lo), "f"(hi)); return r;
}
__device__ __forceinline__ ULL dup2(float v) { return pk2(v, v); }
__device__ __forceinline__ void upk2(ULL v, float& lo, float& hi) {
    asm("mov.b64 {%0,%1},%2;" : "=f"(lo), "=f"(hi) : "l"(v));
}
__device__ __forceinline__ void fma2(ULL& d, ULL a, ULL b) {
    asm("fma.rn.f32x2 %0,%1,%2,%0;" : "+l"(d) : "l"(a), "l"(b));
}
__device__ __forceinline__ ULL mul2(ULL a, ULL b) {
    ULL d; asm("mul.rn.f32x2 %0,%1,%2;" : "=l"(d) : "l"(a), "l"(b)); return d;
}

// ---------------- cp.async helpers ------------------------------------------
__device__ __forceinline__ void cpa16(void* smem_dst, const void* gsrc) {
    unsigned s = (unsigned)__cvta_generic_to_shared(smem_dst);
    asm volatile("cp.async.cg.shared.global [%0],[%1],16;" :: "r"(s), "l"(gsrc));
}
#define CP_COMMIT asm volatile("cp.async.commit_group;")

// ---------------- vector RED ------------------------------------------------
__device__ __forceinline__ void red_v4(float* p, float a, float b, float c, float d) {
    asm volatile("red.global.add.v4.f32 [%0],{%1,%2,%3,%4};"
                 :: "l"(p), "f"(a), "f"(b), "f"(c), "f"(d) : "memory");
}

// ---------------- scratch ----------------------------------------------------
__device__ float g_ef[EE * 8];
__device__ float g_Y[EE * 3];
__device__ float g_sv[NN * 128];    // [n][f]{s,v0,v1,v2} packed float4
__device__ float g_agg[NN * 128];   // same packing

// ---------------- edge geometry ---------------------------------------------
__global__ void geom_kernel(const float* __restrict__ coords,
                            const int* __restrict__ eidx) {
    int e = blockIdx.x * blockDim.x + threadIdx.x;
    if (e >= EE) return;
    int snd = eidx[e];
    int rcv = eidx[EE + e];
    float dx = coords[snd * 3 + 0] - coords[rcv * 3 + 0];
    float dy = coords[snd * 3 + 1] - coords[rcv * 3 + 1];
    float dz = coords[snd * 3 + 2] - coords[rcv * 3 + 2];
    float r = sqrtf(dx * dx + dy * dy + dz * dz + 1e-12f);
    float invr = 1.0f / r;
    float x = r * 0.2f;
    float x3 = x * x * x;
    float x6 = x3 * x3;
    float x7 = x6 * x;
    float x8 = x7 * x;
    float fc = (x < 1.0f) ? (1.0f - 28.0f * x6 + 48.0f * x7 - 21.0f * x8) : 0.0f;
    const float kf = 0.6324555320336759f;
    float c = kf * invr * fc;
    float s1, c1;
    sincosf(3.14159265358979323846f * x, &s1, &c1);
    float twoc = 2.0f * c1;
    float sp = 0.0f, sn = s1;
    g_ef[e * 8 + 0] = c * sn;
#pragma unroll
    for (int i = 1; i < 8; i++) {
        float nx = twoc * sn - sp;
        sp = sn; sn = nx;
        g_ef[e * 8 + i] = c * sn;
    }
    float sc = 1.7320508075688772f * invr;
    g_Y[e * 3 + 0] = sc * dx;
    g_Y[e * 3 + 1] = sc * dy;
    g_Y[e * 3 + 2] = sc * dz;
}

// ---------------- node embedding -------------------------------------------
__global__ void emb_kernel(const float* __restrict__ attrs,
                           const float* __restrict__ W) {
    int gid = blockIdx.x * 256 + threadIdx.x;
    int n = gid >> 5;
    int f = gid & 31;
    float acc = 0.0f;
#pragma unroll 8
    for (int a = 0; a < 64; a++) acc += attrs[n * 64 + a] * W[a * 32 + f];
    ((float4*)g_sv)[gid] = make_float4(acc, 0.0f, 0.0f, 0.0f);
}

// ---------------- fused edge kernel -----------------------------------------
// smem floats: W1 512 | b1 64 | W2 10240 | EF 288(pad) | Y 96 | H 2048 | Wo 5120 | idx 64i
#define EDGE_SMEM_BYTES ((512 + 64 + 10240 + 288 + 96 + 2048 + 5120) * 4 + 64 * 4)

__global__ __launch_bounds__(256) void edge_kernel(
    const int* __restrict__ eidx,
    const float* __restrict__ rW1, const float* __restrict__ rb1,
    const float* __restrict__ rW2) {
    extern __shared__ float sm[];
    float* sW1 = sm;               // [8][64]
    float* sB1 = sW1 + 512;        // [64]
    float* sW2 = sB1 + 64;         // [64][160]
    float* sEF = sW2 + 10240;      // [32][9] padded
    float* sY  = sEF + 288;        // [32][3]
    float* sH  = sY + 96;          // [64][32]  (k-major)
    float* sWo = sH + 2048;        // [32][160]
    int*   sIdx = (int*)(sWo + 5120);

    int tid = threadIdx.x;
    int tx = tid & 31, ty = tid >> 5;
    int nA = ty * 4;

    for (int i = tid; i < 512; i += 256) sW1[i] = rW1[i];
    if (tid < 64) sB1[tid] = rb1[tid];
    for (int i = tid; i < 10240; i += 256) sW2[i] = rW2[i];

    const float INV = 0.17677669529663689f;   // 1/sqrt(32)
    const float4* sv4 = (const float4*)g_sv;

    for (int tile = blockIdx.x; tile < EE / 32; tile += gridDim.x) {
        __syncthreads();
        int ebase = tile * 32;
        sEF[(tid >> 3) * 9 + (tid & 7)] = g_ef[ebase * 8 + tid];
        if (tid < 96) sY[tid] = g_Y[ebase * 3 + tid];
        if (tid >= 96 && tid < 128) sIdx[tid - 96] = eidx[ebase + tid - 96];
        if (tid >= 128 && tid < 160) sIdx[tid - 96] = eidx[EE + ebase + tid - 128];
        __syncthreads();

        // prefetch this warp's 4 edge gathers (latency hidden under GEMM below)
        float4 svj[4];
#pragma unroll
        for (int j = 0; j < 4; j++)
            svj[j] = __ldg(&sv4[(long)sIdx[nA + j] * 32 + tx]);

        // H^T = silu(EF @ W1 + b1)
        for (int idx = tid; idx < 2048; idx += 256) {
            int k = idx >> 5, e = idx & 31;
            float acc = sB1[k];
#pragma unroll
            for (int i = 0; i < 8; i++) acc += sEF[e * 9 + i] * sW1[i * 64 + k];
            sH[k * 32 + e] = acc / (1.0f + expf(-acc));
        }
        __syncthreads();

        // Wout = H @ W2 : packed f32x2 over edge pairs
        {
            ULL acc[2][5];
#pragma unroll
            for (int P = 0; P < 2; P++)
#pragma unroll
                for (int p = 0; p < 5; p++) acc[P][p] = 0ULL;

#pragma unroll 4
            for (int k = 0; k < 64; k++) {
                ULL h0 = *(const ULL*)&sH[k * 32 + nA];
                ULL h1 = *(const ULL*)&sH[k * 32 + nA + 2];
#pragma unroll
                for (int p = 0; p < 5; p++) {
                    ULL w2 = dup2(sW2[k * 160 + p * 32 + tx]);
                    fma2(acc[0][p], h0, w2);
                    fma2(acc[1][p], h1, w2);
                }
            }
#pragma unroll
            for (int P = 0; P < 2; P++)
#pragma unroll
                for (int p = 0; p < 5; p++) {
                    float lo, hi;
                    upk2(acc[P][p], lo, hi);
                    sWo[(nA + 2 * P) * 160 + p * 32 + tx] = lo;
                    sWo[(nA + 2 * P + 1) * 160 + p * 32 + tx] = hi;
                }
        }
        __syncthreads();

        // message + single vector RED per edge
#pragma unroll
        for (int j = 0; j < 4; j++) {
            int e = nA + j;
            int rcv = sIdx[32 + e];
            float y0 = sY[e * 3 + 0], y1 = sY[e * 3 + 1], y2 = sY[e * 3 + 2];
            float w0 = sWo[e * 160 + tx];
            float w1 = sWo[e * 160 + 32 + tx];
            float w2 = sWo[e * 160 + 64 + tx];
            float w3 = sWo[e * 160 + 96 + tx];
            float w4 = sWo[e * 160 + 128 + tx];
            float sj = svj[j].x;
            float vj0 = svj[j].y, vj1 = svj[j].z, vj2 = svj[j].w;
            float dot = vj0 * y0 + vj1 * y1 + vj2 * y2;
            float cx = vj1 * y2 - vj2 * y1;
            float cy = vj2 * y0 - vj0 * y2;
            float cz = vj0 * y1 - vj1 * y0;
            float ms  = (w0 * sj + w3 * dot) * INV;
            float mv0 = (w1 * sj * y0 + w2 * vj0 + w4 * cx) * INV;
            float mv1 = (w1 * sj * y1 + w2 * vj1 + w4 * cy) * INV;
            float mv2 = (w1 * sj * y2 + w2 * vj2 + w4 * cz) * INV;
            red_v4(&g_agg[((long)rcv * 32 + tx) * 4], ms, mv0, mv1, mv2);
        }
    }
}

// ---------------- node update -----------------------------------------------
// smem floats: W 4x1536=6144 | AtT 64x34=2176 | ST 32x34=1088 | VT 96x34=3264 |
//              AgS 1088 | AgV 3264  -> 17024 floats = 68096 B  (3 CTAs/SM)
#define NODE_SMEM_BYTES (17024 * 4)

__device__ __forceinline__ void node_issue_stage(float* dst,
        const float* __restrict__ Ws, const float* __restrict__ Wv,
        int s, int tid) {
    int f = s >> 2, q = s & 3;
    const float4* srcA = (const float4*)(Ws + f * 4096 + q * 1024);
    const float4* srcB = (const float4*)(Wv + f * 2048 + q * 512);
    float4* dA = (float4*)dst;
    float4* dB = (float4*)(dst + 1024);
    cpa16(dA + tid, srcA + tid);
    if (tid < 128) cpa16(dB + tid, srcB + tid);
}

__global__ __launch_bounds__(256, 3) void node_kernel(
    const float* __restrict__ attrs,
    const float* __restrict__ Ls, const float* __restrict__ Lv,
    const float* __restrict__ Ws, const float* __restrict__ Wv) {
    extern __shared__ float sm[];
    float* sW   = sm;            // 4 x 1536 (Ws 16a x 64 | Wv 16a x 32)
    float* sAtT = sm + 6144;     // [a][n] stride 34
    float* sST  = sAtT + 2176;   // [f][n] stride 34
    float* sVT  = sST + 1088;    // [c*32+f][n] stride 34
    float* sAgS = sVT + 3264;
    float* sAgV = sAgS + 1088;

    int tid = threadIdx.x, tx = tid & 31, ty = tid >> 5;
    int base = blockIdx.x * 32;
    int nA = ty * 4;

    // prologue: stages 0,1 in flight
    node_issue_stage(sW + 0 * 1536, Ws, Wv, 0, tid); CP_COMMIT;
    node_issue_stage(sW + 1 * 1536, Ws, Wv, 1, tid); CP_COMMIT;

    const float4* sv4 = (const float4*)g_sv;
    const float4* ag4 = (const float4*)g_agg;
    for (int i = tid; i < 1024; i += 256) {
        int f = i & 31, n = i >> 5;
        float4 a = sv4[(long)(base + n) * 32 + f];
        sST[f * 34 + n] = a.x;
        sVT[f * 34 + n] = a.y;
        sVT[(32 + f) * 34 + n] = a.z;
        sVT[(64 + f) * 34 + n] = a.w;
        float4 b = ag4[(long)(base + n) * 32 + f];
        sAgS[f * 34 + n] = b.x;
        sAgV[f * 34 + n] = b.y;
        sAgV[(32 + f) * 34 + n] = b.z;
        sAgV[(64 + f) * 34 + n] = b.w;
    }
    for (int i = tid; i < 2048; i += 256) {
        int a = i & 63, n = i >> 6;
        sAtT[a * 34 + n] = attrs[(base + n) * 64 + a];
    }

    ULL acc0[2] = {0, 0}, acc1[2] = {0, 0}, acc2[2] = {0, 0},
        acc3[2] = {0, 0}, acc4[2] = {0, 0};

    int qi = 0;
    for (int f = 0; f < 32; f++) {
        float Ls0 = __ldg(&Ls[f * 64 + tx]);
        float Ls1 = __ldg(&Ls[f * 64 + 32 + tx]);
        float Lv0 = __ldg(&Lv[f * 32 + tx]);
        ULL Ls02 = dup2(Ls0), Ls12 = dup2(Ls1), Lv02 = dup2(Lv0);

        ULL sf2[2], v02[2], v12[2], v22[2];
        if (f == 0) __syncthreads();   // node arrays ready (covered by stage barrier afterwards)
#pragma unroll
        for (int P = 0; P < 2; P++) {
            int nn = nA + 2 * P;
            sf2[P] = *(const ULL*)&sST[f * 34 + nn];
            v02[P] = *(const ULL*)&sVT[f * 34 + nn];
            v12[P] = *(const ULL*)&sVT[(32 + f) * 34 + nn];
            v22[P] = *(const ULL*)&sVT[(64 + f) * 34 + nn];
            ULL ag = *(const ULL*)&sAgS[f * 34 + nn];
            fma2(acc0[P], ag, Ls02);
            fma2(acc1[P], ag, Ls12);
            fma2(acc2[P], *(const ULL*)&sAgV[f * 34 + nn], Lv02);
            fma2(acc3[P], *(const ULL*)&sAgV[(32 + f) * 34 + nn], Lv02);
            fma2(acc4[P], *(const ULL*)&sAgV[(64 + f) * 34 + nn], Lv02);
        }

#pragma unroll 1
        for (int q = 0; q < 4; q++, qi++) {
            if (qi + 2 < 128)
                node_issue_stage(sW + ((qi + 2) & 3) * 1536, Ws, Wv, qi + 2, tid);
            CP_COMMIT;
            asm volatile("cp.async.wait_group 2;");
            __syncthreads();

            const float* sWq = sW + (qi & 3) * 1536;
#pragma unroll 4
            for (int aa = 0; aa < 16; aa++) {
                int ag_ = (q * 16 + aa);
                ULL at20 = *(const ULL*)&sAtT[ag_ * 34 + nA];
                ULL at21 = *(const ULL*)&sAtT[ag_ * 34 + nA + 2];
                ULL W02  = dup2(sWq[aa * 64 + tx]);
                ULL W12  = dup2(sWq[aa * 64 + 32 + tx]);
                ULL Wv02 = dup2(sWq[1024 + aa * 32 + tx]);
                {
                    ULL us2 = mul2(sf2[0], at20);
                    ULL tv2 = mul2(at20, Wv02);
                    fma2(acc0[0], us2, W02);
                    fma2(acc1[0], us2, W12);
                    fma2(acc2[0], v02[0], tv2);
                    fma2(acc3[0], v12[0], tv2);
                    fma2(acc4[0], v22[0], tv2);
                }
                {
                    ULL us2 = mul2(sf2[1], at21);
                    ULL tv2 = mul2(at21, Wv02);
                    fma2(acc0[1], us2, W02);
                    fma2(acc1[1], us2, W12);
                    fma2(acc2[1], v02[1], tv2);
                    fma2(acc3[1], v12[1], tv2);
                    fma2(acc4[1], v22[1], tv2);
                }
            }
        }
    }

    // epilogue: silu/sigmoid gate + residual (residual from smem), packed store
#pragma unroll
    for (int P = 0; P < 2; P++) {
        float ft[2], gt[2], a2[2], a3[2], a4[2];
        upk2(acc0[P], ft[0], ft[1]);
        upk2(acc1[P], gt[0], gt[1]);
        upk2(acc2[P], a2[0], a2[1]);
        upk2(acc3[P], a3[0], a3[1]);
        upk2(acc4[P], a4[0], a4[1]);
#pragma unroll
        for (int h = 0; h < 2; h++) {
            int nn = nA + 2 * P + h;
            int gn = base + nn;
            float s_old = sST[tx * 34 + nn];
            float v0o = sVT[tx * 34 + nn];
            float v1o = sVT[(32 + tx) * 34 + nn];
            float v2o = sVT[(64 + tx) * 34 + nn];
            float sg = 1.0f / (1.0f + expf(-gt[h]));
            float s_new = ft[h] / (1.0f + expf(-ft[h])) + s_old;
            ((float4*)g_sv)[(long)gn * 32 + tx] =
                make_float4(s_new, a2[h] * sg + v0o, a3[h] * sg + v1o, a4[h] * sg + v2o);
        }
    }
}

// ---------------- output assembly -------------------------------------------
__global__ void out_kernel(float* __restrict__ out) {
    int idx = blockIdx.x * 256 + threadIdx.x;
    if (idx >= NN * 128) return;
    int n = idx >> 7, j = idx & 127;
    float val;
    if (j < 32) {
        val = g_sv[((long)n * 32 + j) * 4];
    } else {
        int t = j - 32;
        int f = t / 3;
        int c = t - 3 * f;
        val = g_sv[((long)n * 32 + f) * 4 + 1 + c];
    }
    out[idx] = val;
}

// ---------------- launch -----------------------------------------------------
extern "C" void kernel_launch(void* const* d_in, const int* in_sizes, int n_in,
                              void* d_out, int out_size) {
    const float* attrs  = (const float*)d_in[0];
    const float* coords = (const float*)d_in[1];
    const int*   eidx   = (const int*)d_in[2];
    const float* embW   = (const float*)d_in[3];
    const float* rW1    = (const float*)d_in[4];
    const float* rb1    = (const float*)d_in[5];
    const float* rW2    = (const float*)d_in[6];
    const float* Ls     = (const float*)d_in[7];
    const float* Lv     = (const float*)d_in[8];
    const float* Ws     = (const float*)d_in[9];
    const float* Wv     = (const float*)d_in[10];
    float* out = (float*)d_out;

    cudaFuncSetAttribute(edge_kernel,
                         cudaFuncAttributeMaxDynamicSharedMemorySize,
                         EDGE_SMEM_BYTES);
    cudaFuncSetAttribute(node_kernel,
                         cudaFuncAttributeMaxDynamicSharedMemorySize,
                         NODE_SMEM_BYTES);

    void* pagg = nullptr;
    cudaGetSymbolAddress(&pagg, g_agg);

    geom_kernel<<<EE / 256, 256>>>(coords, eidx);
    emb_kernel<<<NN * 32 / 256, 256>>>(attrs, embW);

    for (int l = 0; l < 2; l++) {
        cudaMemsetAsync(pagg, 0, NN * 128 * sizeof(float));
        edge_kernel<<<888, 256, EDGE_SMEM_BYTES>>>(
            eidx, rW1 + l * 512, rb1 + l * 64, rW2 + l * 10240);
        node_kernel<<<625, 256, NODE_SMEM_BYTES>>>(
            attrs, Ls + l * 2048, Lv + l * 1024,
            Ws + l * 131072, Wv + l * 65536);
    }
    out_kernel<<<(NN * 128 + 255) / 256, 256>>>(out);
}

// round 5
// speedup vs baseline: 1.3712x; 1.0008x over previous
#include <cuda_runtime.h>
#include <math.h>

#define NN 20000
#define EE 640000

typedef unsigned long long ULL;

// ---------------- packed f32x2 helpers -------------------------------------
__device__ __forceinline__ ULL pk2(float lo, float hi) {
    ULL r; asm("mov.b64 %0,{%1,%2};" : "=l"(r) : "f"(lo), "f"(hi)); return r;
}
__device__ __forceinline__ ULL dup2(float v) { return pk2(v, v); }
__device__ __forceinline__ void upk2(ULL v, float& lo, float& hi) {
    asm("mov.b64 {%0,%1},%2;" : "=f"(lo), "=f"(hi) : "l"(v));
}
__device__ __forceinline__ void fma2(ULL& d, ULL a, ULL b) {
    asm("fma.rn.f32x2 %0,%1,%2,%0;" : "+l"(d) : "l"(a), "l"(b));
}
__device__ __forceinline__ ULL mul2(ULL a, ULL b) {
    ULL d; asm("mul.rn.f32x2 %0,%1,%2;" : "=l"(d) : "l"(a), "l"(b)); return d;
}

// ---------------- cp.async helpers ------------------------------------------
__device__ __forceinline__ void cpa16(void* smem_dst, const void* gsrc) {
    unsigned s = (unsigned)__cvta_generic_to_shared(smem_dst);
    asm volatile("cp.async.cg.shared.global [%0],[%1],16;" :: "r"(s), "l"(gsrc));
}
#define CP_COMMIT asm volatile("cp.async.commit_group;")

// ---------------- vector RED ------------------------------------------------
__device__ __forceinline__ void red_v4(float* p, float a, float b, float c, float d) {
    asm volatile("red.global.add.v4.f32 [%0],{%1,%2,%3,%4};"
                 :: "l"(p), "f"(a), "f"(b), "f"(c), "f"(d) : "memory");
}

// ---------------- scratch ----------------------------------------------------
__device__ float g_ef[EE * 8];
__device__ float g_Y[EE * 3];
__device__ float g_sv[NN * 128];    // [n][f]{s,v0,v1,v2} packed float4
__device__ float g_agg[NN * 128];   // same packing
__device__ float g_pre[NN * 160];   // [n][p][32] p = {ft, gt, v0, v1, v2}

// ---------------- edge geometry ---------------------------------------------
__global__ void geom_kernel(const float* __restrict__ coords,
                            const int* __restrict__ eidx) {
    int e = blockIdx.x * blockDim.x + threadIdx.x;
    if (e >= EE) return;
    int snd = eidx[e];
    int rcv = eidx[EE + e];
    float dx = coords[snd * 3 + 0] - coords[rcv * 3 + 0];
    float dy = coords[snd * 3 + 1] - coords[rcv * 3 + 1];
    float dz = coords[snd * 3 + 2] - coords[rcv * 3 + 2];
    float r = sqrtf(dx * dx + dy * dy + dz * dz + 1e-12f);
    float invr = 1.0f / r;
    float x = r * 0.2f;
    float x3 = x * x * x;
    float x6 = x3 * x3;
    float x7 = x6 * x;
    float x8 = x7 * x;
    float fc = (x < 1.0f) ? (1.0f - 28.0f * x6 + 48.0f * x7 - 21.0f * x8) : 0.0f;
    const float kf = 0.6324555320336759f;
    float c = kf * invr * fc;
    float s1, c1;
    sincosf(3.14159265358979323846f * x, &s1, &c1);
    float twoc = 2.0f * c1;
    float sp = 0.0f, sn = s1;
    g_ef[e * 8 + 0] = c * sn;
#pragma unroll
    for (int i = 1; i < 8; i++) {
        float nx = twoc * sn - sp;
        sp = sn; sn = nx;
        g_ef[e * 8 + i] = c * sn;
    }
    float sc = 1.7320508075688772f * invr;
    g_Y[e * 3 + 0] = sc * dx;
    g_Y[e * 3 + 1] = sc * dy;
    g_Y[e * 3 + 2] = sc * dz;
}

// ---------------- node embedding -------------------------------------------
__global__ void emb_kernel(const float* __restrict__ attrs,
                           const float* __restrict__ W) {
    int gid = blockIdx.x * 256 + threadIdx.x;
    int n = gid >> 5;
    int f = gid & 31;
    float acc = 0.0f;
#pragma unroll 8
    for (int a = 0; a < 64; a++) acc += attrs[n * 64 + a] * W[a * 32 + f];
    ((float4*)g_sv)[gid] = make_float4(acc, 0.0f, 0.0f, 0.0f);
}

// ---------------- fused edge kernel -----------------------------------------
// smem floats: W1 512 | b1 64 | W2 10240 | EF 288(pad) | Y 96 | H 2048 | idx 64i
#define EDGE_SMEM_BYTES ((512 + 64 + 10240 + 288 + 96 + 2048) * 4 + 64 * 4)

__global__ __launch_bounds__(256, 4) void edge_kernel(
    const int* __restrict__ eidx,
    const float* __restrict__ rW1, const float* __restrict__ rb1,
    const float* __restrict__ rW2) {
    extern __shared__ float sm[];
    float* sW1 = sm;               // [8][64]
    float* sB1 = sW1 + 512;        // [64]
    float* sW2 = sB1 + 64;         // [64][160]
    float* sEF = sW2 + 10240;      // [32][9] padded
    float* sY  = sEF + 288;        // [32][3]
    float* sH  = sY + 96;          // [64][32]  (k-major)
    int*   sIdx = (int*)(sH + 2048);

    int tid = threadIdx.x;
    int tx = tid & 31, ty = tid >> 5;
    int nA = ty * 4;

    for (int i = tid; i < 512; i += 256) sW1[i] = rW1[i];
    if (tid < 64) sB1[tid] = rb1[tid];
    for (int i = tid; i < 10240; i += 256) sW2[i] = rW2[i];

    const float INV = 0.17677669529663689f;   // 1/sqrt(32)
    const float4* sv4 = (const float4*)g_sv;

    for (int tile = blockIdx.x; tile < EE / 32; tile += gridDim.x) {
        __syncthreads();
        int ebase = tile * 32;
        sEF[(tid >> 3) * 9 + (tid & 7)] = g_ef[ebase * 8 + tid];
        if (tid < 96) sY[tid] = g_Y[ebase * 3 + tid];
        if (tid >= 96 && tid < 128) sIdx[tid - 96] = eidx[ebase + tid - 96];
        if (tid >= 128 && tid < 160) sIdx[tid - 96] = eidx[EE + ebase + tid - 128];
        __syncthreads();

        // prefetch this warp's 4 edge gathers (latency hidden under GEMM below)
        float4 svj[4];
#pragma unroll
        for (int j = 0; j < 4; j++)
            svj[j] = __ldg(&sv4[(long)sIdx[nA + j] * 32 + tx]);

        // H^T = silu(EF @ W1 + b1)
        for (int idx = tid; idx < 2048; idx += 256) {
            int k = idx >> 5, e = idx & 31;
            float acc = sB1[k];
#pragma unroll
            for (int i = 0; i < 8; i++) acc += sEF[e * 9 + i] * sW1[i * 64 + k];
            sH[k * 32 + e] = acc / (1.0f + expf(-acc));
        }
        __syncthreads();

        // Wout = H @ W2 : packed f32x2 over edge pairs; accumulators stay in
        // registers — the message phase below consumes exactly this tile.
        float wv[4][5];
        {
            ULL acc[2][5];
#pragma unroll
            for (int P = 0; P < 2; P++)
#pragma unroll
                for (int p = 0; p < 5; p++) acc[P][p] = 0ULL;

#pragma unroll 4
            for (int k = 0; k < 64; k++) {
                ULL h0 = *(const ULL*)&sH[k * 32 + nA];
                ULL h1 = *(const ULL*)&sH[k * 32 + nA + 2];
#pragma unroll
                for (int p = 0; p < 5; p++) {
                    ULL w2 = dup2(sW2[k * 160 + p * 32 + tx]);
                    fma2(acc[0][p], h0, w2);
                    fma2(acc[1][p], h1, w2);
                }
            }
#pragma unroll
            for (int P = 0; P < 2; P++)
#pragma unroll
                for (int p = 0; p < 5; p++)
                    upk2(acc[P][p], wv[2 * P][p], wv[2 * P + 1][p]);
        }

        // message + single vector RED per edge (no barrier needed: same thread)
#pragma unroll
        for (int j = 0; j < 4; j++) {
            int e = nA + j;
            int rcv = sIdx[32 + e];
            float y0 = sY[e * 3 + 0], y1 = sY[e * 3 + 1], y2 = sY[e * 3 + 2];
            float w0 = wv[j][0], w1 = wv[j][1], w2 = wv[j][2],
                  w3 = wv[j][3], w4 = wv[j][4];
            float sj = svj[j].x;
            float vj0 = svj[j].y, vj1 = svj[j].z, vj2 = svj[j].w;
            float dot = vj0 * y0 + vj1 * y1 + vj2 * y2;
            float cx = vj1 * y2 - vj2 * y1;
            float cy = vj2 * y0 - vj0 * y2;
            float cz = vj0 * y1 - vj1 * y0;
            float ms  = (w0 * sj + w3 * dot) * INV;
            float mv0 = (w1 * sj * y0 + w2 * vj0 + w4 * cx) * INV;
            float mv1 = (w1 * sj * y1 + w2 * vj1 + w4 * cy) * INV;
            float mv2 = (w1 * sj * y2 + w2 * vj2 + w4 * cz) * INV;
            red_v4(&g_agg[((long)rcv * 32 + tx) * 4], ms, mv0, mv1, mv2);
        }
    }
}

// ---------------- node update (f-split: 2 CTAs per 32-node tile) ------------
// smem floats: W 4x1536=6144 | AtT 64x34=2176 | ST 16x34=544 | VT 48x34=1632 |
//              AgS 544 | AgV 1632  -> 12672 floats = 50688 B
#define NODE_SMEM_BYTES (12672 * 4)

__device__ __forceinline__ void node_issue_stage(float* dst,
        const float* __restrict__ Ws, const float* __restrict__ Wv,
        int f0, int s, int tid) {
    int f = f0 + (s >> 2), q = s & 3;
    const float4* srcA = (const float4*)(Ws + f * 4096 + q * 1024);
    const float4* srcB = (const float4*)(Wv + f * 2048 + q * 512);
    float4* dA = (float4*)dst;
    float4* dB = (float4*)(dst + 1024);
    cpa16(dA + tid, srcA + tid);
    if (tid < 128) cpa16(dB + tid, srcB + tid);
}

__global__ __launch_bounds__(256, 4) void node_kernel(
    const float* __restrict__ attrs,
    const float* __restrict__ Ls, const float* __restrict__ Lv,
    const float* __restrict__ Ws, const float* __restrict__ Wv) {
    extern __shared__ float sm[];
    float* sW   = sm;            // 4 x 1536 (Ws 16a x 64 | Wv 16a x 32)
    float* sAtT = sm + 6144;     // [a][n] stride 34
    float* sST  = sAtT + 2176;   // [f_local][n] stride 34 (16 rows)
    float* sVT  = sST + 544;     // [c*16+f_local][n] stride 34 (48 rows)
    float* sAgS = sVT + 1632;
    float* sAgV = sAgS + 544;

    int tid = threadIdx.x, tx = tid & 31, ty = tid >> 5;
    int tile = blockIdx.x >> 1;
    int f0 = (blockIdx.x & 1) * 16;
    int base = tile * 32;
    int nA = ty * 4;

    // prologue: stages 0,1 in flight
    node_issue_stage(sW + 0 * 1536, Ws, Wv, f0, 0, tid); CP_COMMIT;
    node_issue_stage(sW + 1 * 1536, Ws, Wv, f0, 1, tid); CP_COMMIT;

    const float4* sv4 = (const float4*)g_sv;
    const float4* ag4 = (const float4*)g_agg;
    for (int i = tid; i < 512; i += 256) {
        int fl = i & 15, n = i >> 4;
        float4 a = sv4[(long)(base + n) * 32 + f0 + fl];
        sST[fl * 34 + n] = a.x;
        sVT[fl * 34 + n] = a.y;
        sVT[(16 + fl) * 34 + n] = a.z;
        sVT[(32 + fl) * 34 + n] = a.w;
        float4 b = ag4[(long)(base + n) * 32 + f0 + fl];
        sAgS[fl * 34 + n] = b.x;
        sAgV[fl * 34 + n] = b.y;
        sAgV[(16 + fl) * 34 + n] = b.z;
        sAgV[(32 + fl) * 34 + n] = b.w;
    }
    for (int i = tid; i < 2048; i += 256) {
        int a = i & 63, n = i >> 6;
        sAtT[a * 34 + n] = attrs[(base + n) * 64 + a];
    }

    ULL acc0[2] = {0, 0}, acc1[2] = {0, 0}, acc2[2] = {0, 0},
        acc3[2] = {0, 0}, acc4[2] = {0, 0};

    int qi = 0;
    for (int fl = 0; fl < 16; fl++) {
        int fg = f0 + fl;
        float Ls0 = __ldg(&Ls[fg * 64 + tx]);
        float Ls1 = __ldg(&Ls[fg * 64 + 32 + tx]);
        float Lv0 = __ldg(&Lv[fg * 32 + tx]);
        ULL Ls02 = dup2(Ls0), Ls12 = dup2(Ls1), Lv02 = dup2(Lv0);

        ULL sf2[2], v02[2], v12[2], v22[2];
        if (fl == 0) __syncthreads();   // node arrays ready
#pragma unroll
        for (int P = 0; P < 2; P++) {
            int nn = nA + 2 * P;
            sf2[P] = *(const ULL*)&sST[fl * 34 + nn];
            v02[P] = *(const ULL*)&sVT[fl * 34 + nn];
            v12[P] = *(const ULL*)&sVT[(16 + fl) * 34 + nn];
            v22[P] = *(const ULL*)&sVT[(32 + fl) * 34 + nn];
            ULL ag = *(const ULL*)&sAgS[fl * 34 + nn];
            fma2(acc0[P], ag, Ls02);
            fma2(acc1[P], ag, Ls12);
            fma2(acc2[P], *(const ULL*)&sAgV[fl * 34 + nn], Lv02);
            fma2(acc3[P], *(const ULL*)&sAgV[(16 + fl) * 34 + nn], Lv02);
            fma2(acc4[P], *(const ULL*)&sAgV[(32 + fl) * 34 + nn], Lv02);
        }

#pragma unroll 1
        for (int q = 0; q < 4; q++, qi++) {
            if (qi + 2 < 64)
                node_issue_stage(sW + ((qi + 2) & 3) * 1536, Ws, Wv, f0, qi + 2, tid);
            CP_COMMIT;
            asm volatile("cp.async.wait_group 2;");
            __syncthreads();

            const float* sWq = sW + (qi & 3) * 1536;
#pragma unroll 4
            for (int aa = 0; aa < 16; aa++) {
                int ag_ = (q * 16 + aa);
                ULL at20 = *(const ULL*)&sAtT[ag_ * 34 + nA];
                ULL at21 = *(const ULL*)&sAtT[ag_ * 34 + nA + 2];
                ULL W02  = dup2(sWq[aa * 64 + tx]);
                ULL W12  = dup2(sWq[aa * 64 + 32 + tx]);
                ULL Wv02 = dup2(sWq[1024 + aa * 32 + tx]);
                {
                    ULL us2 = mul2(sf2[0], at20);
                    ULL tv2 = mul2(at20, Wv02);
                    fma2(acc0[0], us2, W02);
                    fma2(acc1[0], us2, W12);
                    fma2(acc2[0], v02[0], tv2);
                    fma2(acc3[0], v12[0], tv2);
                    fma2(acc4[0], v22[0], tv2);
                }
                {
                    ULL us2 = mul2(sf2[1], at21);
                    ULL tv2 = mul2(at21, Wv02);
                    fma2(acc0[1], us2, W02);
                    fma2(acc1[1], us2, W12);
                    fma2(acc2[1], v02[1], tv2);
                    fma2(acc3[1], v12[1], tv2);
                    fma2(acc4[1], v22[1], tv2);
                }
            }
        }
    }

    // epilogue: RED partial sums into g_pre (coalesced across lanes)
#pragma unroll
    for (int P = 0; P < 2; P++) {
        float ft[2], gt[2], a2[2], a3[2], a4[2];
        upk2(acc0[P], ft[0], ft[1]);
        upk2(acc1[P], gt[0], gt[1]);
        upk2(acc2[P], a2[0], a2[1]);
        upk2(acc3[P], a3[0], a3[1]);
        upk2(acc4[P], a4[0], a4[1]);
#pragma unroll
        for (int h = 0; h < 2; h++) {
            int gn = base + nA + 2 * P + h;
            float* p = g_pre + (long)gn * 160 + tx;
            atomicAdd(p, ft[h]);
            atomicAdd(p + 32, gt[h]);
            atomicAdd(p + 64, a2[h]);
            atomicAdd(p + 96, a3[h]);
            atomicAdd(p + 128, a4[h]);
        }
    }
}

// ---------------- node epilogue: activation + gate + residual ---------------
__global__ void epi_kernel() {
    int idx = blockIdx.x * 256 + threadIdx.x;
    if (idx >= NN * 32) return;
    int n = idx >> 5, tx = idx & 31;
    const float* p = g_pre + (long)n * 160 + tx;
    float ft = p[0], gt = p[32], a2 = p[64], a3 = p[96], a4 = p[128];
    float4 o = ((float4*)g_sv)[idx];
    float sg = 1.0f / (1.0f + expf(-gt));
    float s_new = ft / (1.0f + expf(-ft)) + o.x;
    ((float4*)g_sv)[idx] =
        make_float4(s_new, a2 * sg + o.y, a3 * sg + o.z, a4 * sg + o.w);
}

// ---------------- output assembly -------------------------------------------
__global__ void out_kernel(float* __restrict__ out) {
    int idx = blockIdx.x * 256 + threadIdx.x;
    if (idx >= NN * 128) return;
    int n = idx >> 7, j = idx & 127;
    float val;
    if (j < 32) {
        val = g_sv[((long)n * 32 + j) * 4];
    } else {
        int t = j - 32;
        int f = t / 3;
        int c = t - 3 * f;
        val = g_sv[((long)n * 32 + f) * 4 + 1 + c];
    }
    out[idx] = val;
}

// ---------------- launch -----------------------------------------------------
extern "C" void kernel_launch(void* const* d_in, const int* in_sizes, int n_in,
                              void* d_out, int out_size) {
    const float* attrs  = (const float*)d_in[0];
    const float* coords = (const float*)d_in[1];
    const int*   eidx   = (const int*)d_in[2];
    const float* embW   = (const float*)d_in[3];
    const float* rW1    = (const float*)d_in[4];
    const float* rb1    = (const float*)d_in[5];
    const float* rW2    = (const float*)d_in[6];
    const float* Ls     = (const float*)d_in[7];
    const float* Lv     = (const float*)d_in[8];
    const float* Ws     = (const float*)d_in[9];
    const float* Wv     = (const float*)d_in[10];
    float* out = (float*)d_out;

    cudaFuncSetAttribute(edge_kernel,
                         cudaFuncAttributeMaxDynamicSharedMemorySize,
                         EDGE_SMEM_BYTES);
    cudaFuncSetAttribute(node_kernel,
                         cudaFuncAttributeMaxDynamicSharedMemorySize,
                         NODE_SMEM_BYTES);

    void* pagg = nullptr;
    void* ppre = nullptr;
    cudaGetSymbolAddress(&pagg, g_agg);
    cudaGetSymbolAddress(&ppre, g_pre);

    geom_kernel<<<EE / 256, 256>>>(coords, eidx);
    emb_kernel<<<NN * 32 / 256, 256>>>(attrs, embW);

    for (int l = 0; l < 2; l++) {
        cudaMemsetAsync(pagg, 0, NN * 128 * sizeof(float));
        cudaMemsetAsync(ppre, 0, NN * 160 * sizeof(float));
        edge_kernel<<<592, 256, EDGE_SMEM_BYTES>>>(
            eidx, rW1 + l * 512, rb1 + l * 64, rW2 + l * 10240);
        node_kernel<<<1250, 256, NODE_SMEM_BYTES>>>(
            attrs, Ls + l * 2048, Lv + l * 1024,
            Ws + l * 131072, Wv + l * 65536);
        epi_kernel<<<(NN * 32 + 255) / 256, 256>>>();
    }
    out_kernel<<<(NN * 128 + 255) / 256, 256>>>(out);
}

// round 6
// speedup vs baseline: 1.4537x; 1.0601x over previous
#include <cuda_runtime.h>
#include <math.h>

#define NN 20000
#define EE 640000

typedef unsigned long long ULL;

// ---------------- packed f32x2 helpers -------------------------------------
__device__ __forceinline__ ULL pk2(float lo, float hi) {
    ULL r; asm("mov.b64 %0,{%1,%2};" : "=l"(r) : "f"(lo), "f"(hi)); return r;
}
__device__ __forceinline__ ULL dup2(float v) { return pk2(v, v); }
__device__ __forceinline__ void upk2(ULL v, float& lo, float& hi) {
    asm("mov.b64 {%0,%1},%2;" : "=f"(lo), "=f"(hi) : "l"(v));
}
__device__ __forceinline__ void fma2(ULL& d, ULL a, ULL b) {
    asm("fma.rn.f32x2 %0,%1,%2,%0;" : "+l"(d) : "l"(a), "l"(b));
}
__device__ __forceinline__ ULL mul2(ULL a, ULL b) {
    ULL d; asm("mul.rn.f32x2 %0,%1,%2;" : "=l"(d) : "l"(a), "l"(b)); return d;
}

// ---------------- cp.async helpers ------------------------------------------
__device__ __forceinline__ void cpa16(void* smem_dst, const void* gsrc) {
    unsigned s = (unsigned)__cvta_generic_to_shared(smem_dst);
    asm volatile("cp.async.cg.shared.global [%0],[%1],16;" :: "r"(s), "l"(gsrc));
}
#define CP_COMMIT asm volatile("cp.async.commit_group;")

// ---------------- vector RED ------------------------------------------------
__device__ __forceinline__ void red_v4(float* p, float a, float b, float c, float d) {
    asm volatile("red.global.add.v4.f32 [%0],{%1,%2,%3,%4};"
                 :: "l"(p), "f"(a), "f"(b), "f"(c), "f"(d) : "memory");
}

__device__ __forceinline__ float fsilu(float x) {
    return x * __fdividef(1.0f, 1.0f + __expf(-x));
}
__device__ __forceinline__ float fsig(float x) {
    return __fdividef(1.0f, 1.0f + __expf(-x));
}

// ---------------- scratch ----------------------------------------------------
__device__ float g_ef[EE * 8];
__device__ float g_Y[EE * 3];
__device__ float g_sv[NN * 128];    // [n][f]{s,v0,v1,v2} packed float4
__device__ float g_agg[NN * 128];   // same packing
__device__ float g_pre[NN * 160];   // [n][p][32] p = {ft, gt, v0, v1, v2}
__device__ float g_wdup[786432];    // duplicated node weights, 2 layers

// ---------------- weight duplication (runs once) ----------------------------
__global__ void dupw_kernel(const float* __restrict__ Ws,
                            const float* __restrict__ Wv) {
    int idx = blockIdx.x * 256 + threadIdx.x;   // < 786432
    int l = idx / 393216;
    int rem = idx - l * 393216;
    int f = rem / 12288;
    int a = (rem / 192) % 64;
    int c = rem % 192;
    float v;
    if (c < 128)
        v = Ws[(long)l * 131072 + f * 4096 + a * 64 + (c >> 1)];
    else
        v = Wv[(long)l * 65536 + f * 2048 + a * 32 + ((c - 128) >> 1)];
    g_wdup[idx] = v;
}

// ---------------- edge geometry ---------------------------------------------
__global__ void geom_kernel(const float* __restrict__ coords,
                            const int* __restrict__ eidx) {
    int e = blockIdx.x * blockDim.x + threadIdx.x;
    if (e >= EE) return;
    int snd = eidx[e];
    int rcv = eidx[EE + e];
    float dx = coords[snd * 3 + 0] - coords[rcv * 3 + 0];
    float dy = coords[snd * 3 + 1] - coords[rcv * 3 + 1];
    float dz = coords[snd * 3 + 2] - coords[rcv * 3 + 2];
    float r = sqrtf(dx * dx + dy * dy + dz * dz + 1e-12f);
    float invr = 1.0f / r;
    float x = r * 0.2f;
    float x3 = x * x * x;
    float x6 = x3 * x3;
    float x7 = x6 * x;
    float x8 = x7 * x;
    float fc = (x < 1.0f) ? (1.0f - 28.0f * x6 + 48.0f * x7 - 21.0f * x8) : 0.0f;
    const float kf = 0.6324555320336759f;
    float c = kf * invr * fc;
    float s1, c1;
    sincosf(3.14159265358979323846f * x, &s1, &c1);
    float twoc = 2.0f * c1;
    float sp = 0.0f, sn = s1;
    g_ef[e * 8 + 0] = c * sn;
#pragma unroll
    for (int i = 1; i < 8; i++) {
        float nx = twoc * sn - sp;
        sp = sn; sn = nx;
        g_ef[e * 8 + i] = c * sn;
    }
    float sc = 1.7320508075688772f * invr;
    g_Y[e * 3 + 0] = sc * dx;
    g_Y[e * 3 + 1] = sc * dy;
    g_Y[e * 3 + 2] = sc * dz;
}

// ---------------- node embedding -------------------------------------------
__global__ void emb_kernel(const float* __restrict__ attrs,
                           const float* __restrict__ W) {
    int gid = blockIdx.x * 256 + threadIdx.x;
    int n = gid >> 5;
    int f = gid & 31;
    float acc = 0.0f;
#pragma unroll 8
    for (int a = 0; a < 64; a++) acc += attrs[n * 64 + a] * W[a * 32 + f];
    ((float4*)g_sv)[gid] = make_float4(acc, 0.0f, 0.0f, 0.0f);
}

// ---------------- fused edge kernel (64-edge tiles, j=8) --------------------
// smem floats: W1 512 | b1 64 | W2 10240 | EF 576(pad9) | Y 192 | H 4096 | idx 128i
#define EDGE_SMEM_BYTES ((512 + 64 + 10240 + 576 + 192 + 4096) * 4 + 128 * 4)

__global__ __launch_bounds__(256, 3) void edge_kernel(
    const int* __restrict__ eidx,
    const float* __restrict__ rW1, const float* __restrict__ rb1,
    const float* __restrict__ rW2) {
    extern __shared__ float sm[];
    float* sW1 = sm;               // [8][64]
    float* sB1 = sW1 + 512;        // [64]
    float* sW2 = sB1 + 64;         // [64][160]
    float* sEF = sW2 + 10240;      // [64][9] padded
    float* sY  = sEF + 576;        // [64][3]
    float* sH  = sY + 192;         // [64k][64e]
    int*   sIdx = (int*)(sH + 4096);  // snd[64], rcv[64]

    int tid = threadIdx.x;
    int tx = tid & 31, ty = tid >> 5;
    int eb = ty * 8;

    for (int i = tid; i < 512; i += 256) sW1[i] = rW1[i];
    if (tid < 64) sB1[tid] = rb1[tid];
    for (int i = tid; i < 10240; i += 256) sW2[i] = rW2[i];

    const float INV = 0.17677669529663689f;   // 1/sqrt(32)
    const float4* sv4 = (const float4*)g_sv;

    for (int tile = blockIdx.x; tile < EE / 64; tile += gridDim.x) {
        __syncthreads();
        int ebase = tile * 64;
#pragma unroll
        for (int t = 0; t < 2; t++) {
            int i = tid + t * 256;
            sEF[(i >> 3) * 9 + (i & 7)] = g_ef[ebase * 8 + i];
        }
        if (tid < 192) sY[tid] = g_Y[ebase * 3 + tid];
        if (tid < 64) sIdx[tid] = eidx[ebase + tid];
        else if (tid < 128) sIdx[tid] = eidx[EE + ebase + tid - 64];
        __syncthreads();

        // H^T = silu(EF @ W1 + b1): 4096 outputs, 16/thread
        for (int idx = tid; idx < 4096; idx += 256) {
            int k = idx >> 6, e = idx & 63;
            float acc = sB1[k];
#pragma unroll
            for (int i = 0; i < 8; i++) acc += sEF[e * 9 + i] * sW1[i * 64 + k];
            sH[k * 64 + e] = fsilu(acc);
        }
        __syncthreads();

        // Wout = H @ W2 : 8 edges x 5 outputs per thread, packed edge pairs
        ULL acc[4][5];
#pragma unroll
        for (int jj = 0; jj < 4; jj++)
#pragma unroll
            for (int p = 0; p < 5; p++) acc[jj][p] = 0ULL;

#pragma unroll 2
        for (int k = 0; k < 64; k++) {
            ULL h[4];
#pragma unroll
            for (int jj = 0; jj < 4; jj++)
                h[jj] = *(const ULL*)&sH[k * 64 + eb + 2 * jj];
#pragma unroll
            for (int p = 0; p < 5; p++) {
                ULL w2 = dup2(sW2[k * 160 + p * 32 + tx]);
#pragma unroll
                for (int jj = 0; jj < 4; jj++) fma2(acc[jj][p], h[jj], w2);
            }
        }

        // message phase: pairs of edges, software-pipelined gathers
        float4 cur0 = __ldg(&sv4[(long)sIdx[eb] * 32 + tx]);
        float4 cur1 = __ldg(&sv4[(long)sIdx[eb + 1] * 32 + tx]);
#pragma unroll
        for (int jj = 0; jj < 4; jj++) {
            float4 nxt0, nxt1;
            if (jj < 3) {
                nxt0 = __ldg(&sv4[(long)sIdx[eb + 2 * jj + 2] * 32 + tx]);
                nxt1 = __ldg(&sv4[(long)sIdx[eb + 2 * jj + 3] * 32 + tx]);
            }
            float wlo[5], whi[5];
#pragma unroll
            for (int p = 0; p < 5; p++) upk2(acc[jj][p], wlo[p], whi[p]);
#pragma unroll
            for (int h2 = 0; h2 < 2; h2++) {
                int e = eb + 2 * jj + h2;
                int rcv = sIdx[64 + e];
                float y0 = sY[e * 3 + 0], y1 = sY[e * 3 + 1], y2 = sY[e * 3 + 2];
                const float* w = h2 ? whi : wlo;
                float4 sv = h2 ? cur1 : cur0;
                float sj = sv.x, vj0 = sv.y, vj1 = sv.z, vj2 = sv.w;
                float dot = vj0 * y0 + vj1 * y1 + vj2 * y2;
                float cx = vj1 * y2 - vj2 * y1;
                float cy = vj2 * y0 - vj0 * y2;
                float cz = vj0 * y1 - vj1 * y0;
                float ms  = (w[0] * sj + w[3] * dot) * INV;
                float mv0 = (w[1] * sj * y0 + w[2] * vj0 + w[4] * cx) * INV;
                float mv1 = (w[1] * sj * y1 + w[2] * vj1 + w[4] * cy) * INV;
                float mv2 = (w[1] * sj * y2 + w[2] * vj2 + w[4] * cz) * INV;
                red_v4(&g_agg[((long)rcv * 32 + tx) * 4], ms, mv0, mv1, mv2);
            }
            cur0 = nxt0; cur1 = nxt1;
        }
    }
}

// ---------------- node update (f-split 2, pre-duplicated weights) -----------
// smem floats: W 4x3072=12288 | AtT 64x34=2176 | ST 16x34=544 | VT 48x34=1632 |
//              AgS 544 | AgV 1632  -> 18816 floats = 75264 B  (3 CTAs/SM)
#define NODE_SMEM_BYTES (18816 * 4)

__device__ __forceinline__ void node_issue_stage(float* dst,
        const float* __restrict__ Wd, int s, int tid) {
    const float4* src = (const float4*)(Wd + s * 3072);
    float4* d = (float4*)dst;
#pragma unroll
    for (int i = 0; i < 3; i++) cpa16(d + tid + i * 256, src + tid + i * 256);
}

__global__ __launch_bounds__(256, 3) void node_kernel(
    const float* __restrict__ attrs,
    const float* __restrict__ Ls, const float* __restrict__ Lv,
    const float* __restrict__ Wdup) {
    extern __shared__ float sm[];
    float* sW   = sm;            // 4 x 3072 (16a x [Wsdup128|Wvdup64])
    float* sAtT = sm + 12288;    // [a][n] stride 34
    float* sST  = sAtT + 2176;   // [f_local][n] stride 34 (16 rows)
    float* sVT  = sST + 544;     // [c*16+f_local][n] stride 34 (48 rows)
    float* sAgS = sVT + 1632;
    float* sAgV = sAgS + 544;

    int tid = threadIdx.x, tx = tid & 31, ty = tid >> 5;
    int tile = blockIdx.x >> 1;
    int f0 = (blockIdx.x & 1) * 16;
    int base = tile * 32;
    int nA = ty * 4;
    const float* Wd = Wdup + (long)f0 * 12288;   // stage s covers f0 + s/4

    node_issue_stage(sW + 0 * 3072, Wd, 0, tid); CP_COMMIT;
    node_issue_stage(sW + 1 * 3072, Wd, 1, tid); CP_COMMIT;

    const float4* sv4 = (const float4*)g_sv;
    const float4* ag4 = (const float4*)g_agg;
    for (int i = tid; i < 512; i += 256) {
        int fl = i & 15, n = i >> 4;
        float4 a = sv4[(long)(base + n) * 32 + f0 + fl];
        sST[fl * 34 + n] = a.x;
        sVT[fl * 34 + n] = a.y;
        sVT[(16 + fl) * 34 + n] = a.z;
        sVT[(32 + fl) * 34 + n] = a.w;
        float4 b = ag4[(long)(base + n) * 32 + f0 + fl];
        sAgS[fl * 34 + n] = b.x;
        sAgV[fl * 34 + n] = b.y;
        sAgV[(16 + fl) * 34 + n] = b.z;
        sAgV[(32 + fl) * 34 + n] = b.w;
    }
    for (int i = tid; i < 2048; i += 256) {
        int a = i & 63, n = i >> 6;
        sAtT[a * 34 + n] = attrs[(base + n) * 64 + a];
    }

    ULL acc0[2] = {0, 0}, acc1[2] = {0, 0}, acc2[2] = {0, 0},
        acc3[2] = {0, 0}, acc4[2] = {0, 0};

    int qi = 0;
    for (int fl = 0; fl < 16; fl++) {
        int fg = f0 + fl;
        ULL Ls02 = dup2(__ldg(&Ls[fg * 64 + tx]));
        ULL Ls12 = dup2(__ldg(&Ls[fg * 64 + 32 + tx]));
        ULL Lv02 = dup2(__ldg(&Lv[fg * 32 + tx]));

        ULL sf2[2], v02[2], v12[2], v22[2];
        if (fl == 0) __syncthreads();   // node arrays ready
#pragma unroll
        for (int P = 0; P < 2; P++) {
            int nn = nA + 2 * P;
            sf2[P] = *(const ULL*)&sST[fl * 34 + nn];
            v02[P] = *(const ULL*)&sVT[fl * 34 + nn];
            v12[P] = *(const ULL*)&sVT[(16 + fl) * 34 + nn];
            v22[P] = *(const ULL*)&sVT[(32 + fl) * 34 + nn];
            ULL ag = *(const ULL*)&sAgS[fl * 34 + nn];
            fma2(acc0[P], ag, Ls02);
            fma2(acc1[P], ag, Ls12);
            fma2(acc2[P], *(const ULL*)&sAgV[fl * 34 + nn], Lv02);
            fma2(acc3[P], *(const ULL*)&sAgV[(16 + fl) * 34 + nn], Lv02);
            fma2(acc4[P], *(const ULL*)&sAgV[(32 + fl) * 34 + nn], Lv02);
        }

#pragma unroll 1
        for (int q = 0; q < 4; q++, qi++) {
            if (qi + 2 < 64)
                node_issue_stage(sW + ((qi + 2) & 3) * 3072, Wd, qi + 2, tid);
            CP_COMMIT;
            asm volatile("cp.async.wait_group 2;");
            __syncthreads();

            const float* sWq = sW + (qi & 3) * 3072;
#pragma unroll 4
            for (int aa = 0; aa < 16; aa++) {
                int ag_ = (q * 16 + aa);
                ULL at20 = *(const ULL*)&sAtT[ag_ * 34 + nA];
                ULL at21 = *(const ULL*)&sAtT[ag_ * 34 + nA + 2];
                ULL W02  = *(const ULL*)&sWq[aa * 192 + tx * 2];
                ULL W12  = *(const ULL*)&sWq[aa * 192 + 64 + tx * 2];
                ULL Wv02 = *(const ULL*)&sWq[aa * 192 + 128 + tx * 2];
                {
                    ULL us2 = mul2(sf2[0], at20);
                    ULL tv2 = mul2(at20, Wv02);
                    fma2(acc0[0], us2, W02);
                    fma2(acc1[0], us2, W12);
                    fma2(acc2[0], v02[0], tv2);
                    fma2(acc3[0], v12[0], tv2);
                    fma2(acc4[0], v22[0], tv2);
                }
                {
                    ULL us2 = mul2(sf2[1], at21);
                    ULL tv2 = mul2(at21, Wv02);
                    fma2(acc0[1], us2, W02);
                    fma2(acc1[1], us2, W12);
                    fma2(acc2[1], v02[1], tv2);
                    fma2(acc3[1], v12[1], tv2);
                    fma2(acc4[1], v22[1], tv2);
                }
            }
        }
    }

    // epilogue: RED partial sums into g_pre
#pragma unroll
    for (int P = 0; P < 2; P++) {
        float ft[2], gt[2], a2[2], a3[2], a4[2];
        upk2(acc0[P], ft[0], ft[1]);
        upk2(acc1[P], gt[0], gt[1]);
        upk2(acc2[P], a2[0], a2[1]);
        upk2(acc3[P], a3[0], a3[1]);
        upk2(acc4[P], a4[0], a4[1]);
#pragma unroll
        for (int h = 0; h < 2; h++) {
            int gn = base + nA + 2 * P + h;
            float* p = g_pre + (long)gn * 160 + tx;
            atomicAdd(p, ft[h]);
            atomicAdd(p + 32, gt[h]);
            atomicAdd(p + 64, a2[h]);
            atomicAdd(p + 96, a3[h]);
            atomicAdd(p + 128, a4[h]);
        }
    }
}

// ---------------- node epilogue: activation + gate + residual ---------------
__global__ void epi_kernel() {
    int idx = blockIdx.x * 256 + threadIdx.x;
    if (idx >= NN * 32) return;
    int n = idx >> 5, tx = idx & 31;
    const float* p = g_pre + (long)n * 160 + tx;
    float ft = p[0], gt = p[32], a2 = p[64], a3 = p[96], a4 = p[128];
    float4 o = ((float4*)g_sv)[idx];
    float sg = fsig(gt);
    float s_new = fsilu(ft) + o.x;
    ((float4*)g_sv)[idx] =
        make_float4(s_new, a2 * sg + o.y, a3 * sg + o.z, a4 * sg + o.w);
}

// ---------------- output assembly -------------------------------------------
__global__ void out_kernel(float* __restrict__ out) {
    int idx = blockIdx.x * 256 + threadIdx.x;
    if (idx >= NN * 128) return;
    int n = idx >> 7, j = idx & 127;
    float val;
    if (j < 32) {
        val = g_sv[((long)n * 32 + j) * 4];
    } else {
        int t = j - 32;
        int f = t / 3;
        int c = t - 3 * f;
        val = g_sv[((long)n * 32 + f) * 4 + 1 + c];
    }
    out[idx] = val;
}

// ---------------- launch -----------------------------------------------------
extern "C" void kernel_launch(void* const* d_in, const int* in_sizes, int n_in,
                              void* d_out, int out_size) {
    const float* attrs  = (const float*)d_in[0];
    const float* coords = (const float*)d_in[1];
    const int*   eidx   = (const int*)d_in[2];
    const float* embW   = (const float*)d_in[3];
    const float* rW1    = (const float*)d_in[4];
    const float* rb1    = (const float*)d_in[5];
    const float* rW2    = (const float*)d_in[6];
    const float* Ls     = (const float*)d_in[7];
    const float* Lv     = (const float*)d_in[8];
    const float* Ws     = (const float*)d_in[9];
    const float* Wv     = (const float*)d_in[10];
    float* out = (float*)d_out;

    cudaFuncSetAttribute(edge_kernel,
                         cudaFuncAttributeMaxDynamicSharedMemorySize,
                         EDGE_SMEM_BYTES);
    cudaFuncSetAttribute(node_kernel,
                         cudaFuncAttributeMaxDynamicSharedMemorySize,
                         NODE_SMEM_BYTES);

    void* pagg = nullptr;
    void* ppre = nullptr;
    void* pwd = nullptr;
    cudaGetSymbolAddress(&pagg, g_agg);
    cudaGetSymbolAddress(&ppre, g_pre);
    cudaGetSymbolAddress(&pwd, g_wdup);

    dupw_kernel<<<3072, 256>>>(Ws, Wv);
    geom_kernel<<<EE / 256, 256>>>(coords, eidx);
    emb_kernel<<<NN * 32 / 256, 256>>>(attrs, embW);

    for (int l = 0; l < 2; l++) {
        cudaMemsetAsync(pagg, 0, NN * 128 * sizeof(float));
        cudaMemsetAsync(ppre, 0, NN * 160 * sizeof(float));
        edge_kernel<<<444, 256, EDGE_SMEM_BYTES>>>(
            eidx, rW1 + l * 512, rb1 + l * 64, rW2 + l * 10240);
        node_kernel<<<1250, 256, NODE_SMEM_BYTES>>>(
            attrs, Ls + l * 2048, Lv + l * 1024,
            (const float*)pwd + (long)l * 393216);
        epi_kernel<<<(NN * 32 + 255) / 256, 256>>>();
    }
    out_kernel<<<(NN * 128 + 255) / 256, 256>>>(out);
}

// round 7
// speedup vs baseline: 2.1567x; 1.4836x over previous
#include <cuda_runtime.h>
#include <math.h>

#define NN 20000
#define EE 640000
#define TT 4096

typedef unsigned long long ULL;

// ---------------- packed f32x2 helpers -------------------------------------
__device__ __forceinline__ ULL pk2(float lo, float hi) {
    ULL r; asm("mov.b64 %0,{%1,%2};" : "=l"(r) : "f"(lo), "f"(hi)); return r;
}
__device__ __forceinline__ ULL dup2(float v) { return pk2(v, v); }
__device__ __forceinline__ void upk2(ULL v, float& lo, float& hi) {
    asm("mov.b64 {%0,%1},%2;" : "=f"(lo), "=f"(hi) : "l"(v));
}
__device__ __forceinline__ void fma2(ULL& d, ULL a, ULL b) {
    asm("fma.rn.f32x2 %0,%1,%2,%0;" : "+l"(d) : "l"(a), "l"(b));
}
__device__ __forceinline__ ULL mul2(ULL a, ULL b) {
    ULL d; asm("mul.rn.f32x2 %0,%1,%2;" : "=l"(d) : "l"(a), "l"(b)); return d;
}

// ---------------- cp.async helpers ------------------------------------------
__device__ __forceinline__ void cpa16(void* smem_dst, const void* gsrc) {
    unsigned s = (unsigned)__cvta_generic_to_shared(smem_dst);
    asm volatile("cp.async.cg.shared.global [%0],[%1],16;" :: "r"(s), "l"(gsrc));
}
#define CP_COMMIT asm volatile("cp.async.commit_group;")

// ---------------- vector RED ------------------------------------------------
__device__ __forceinline__ void red_v4(float* p, float a, float b, float c, float d) {
    asm volatile("red.global.add.v4.f32 [%0],{%1,%2,%3,%4};"
                 :: "l"(p), "f"(a), "f"(b), "f"(c), "f"(d) : "memory");
}

__device__ __forceinline__ float fsilu(float x) {
    return x * __fdividef(1.0f, 1.0f + __expf(-x));
}
__device__ __forceinline__ float fsig(float x) {
    return __fdividef(1.0f, 1.0f + __expf(-x));
}

// ---------------- scratch ----------------------------------------------------
__device__ float4 g_geo[EE];        // {x, Y0, Y1, Y2}
__device__ int2   g_se[EE];         // {snd, rcv}
__device__ float  g_sv[NN * 128];   // [n][f]{s,v0,v1,v2} packed float4
__device__ float  g_agg[NN * 128];  // same packing
__device__ float  g_pre[NN * 160];  // [n][p][32]
__device__ float  g_wdup[786432];   // duplicated node weights, 2 layers
__device__ float  g_tab[2 * TT * 160];  // radial lookup: w_p(x) per layer

// ---------------- radial table build (runs once, 2*4096 points) -------------
__global__ void tab_kernel(const float* __restrict__ rW1,
                           const float* __restrict__ rb1,
                           const float* __restrict__ rW2) {
    int l = blockIdx.x >> 12;
    int i = blockIdx.x & (TT - 1);
    int tid = threadIdx.x;       // 160 threads
    __shared__ float H[64];
    float x = (float)i * (1.0f / (float)(TT - 1));
    float xe = fmaxf(x, 1e-7f);
    if (tid < 64) {
        float r = 5.0f * xe;
        float x3 = xe * xe * xe;
        float x6 = x3 * x3;
        float x7 = x6 * xe;
        float x8 = x7 * xe;
        float fc = (xe < 1.0f) ? (1.0f - 28.0f * x6 + 48.0f * x7 - 21.0f * x8) : 0.0f;
        float c = 0.6324555320336759f * fc / r;
        float acc = rb1[l * 64 + tid];
#pragma unroll
        for (int n = 1; n <= 8; n++) {
            float ef = c * sinf((float)n * 3.14159265358979323846f * xe);
            acc += ef * rW1[l * 512 + (n - 1) * 64 + tid];
        }
        H[tid] = acc / (1.0f + expf(-acc));   // exact silu for table
    }
    __syncthreads();
    float out = 0.0f;
#pragma unroll 8
    for (int k = 0; k < 64; k++)
        out += H[k] * rW2[l * 10240 + k * 160 + tid];
    g_tab[((long)l * TT + i) * 160 + tid] = out;
}

// ---------------- weight duplication (runs once) ----------------------------
__global__ void dupw_kernel(const float* __restrict__ Ws,
                            const float* __restrict__ Wv) {
    int idx = blockIdx.x * 256 + threadIdx.x;   // < 786432
    int l = idx / 393216;
    int rem = idx - l * 393216;
    int f = rem / 12288;
    int a = (rem / 192) % 64;
    int c = rem % 192;
    float v;
    if (c < 128)
        v = Ws[(long)l * 131072 + f * 4096 + a * 64 + (c >> 1)];
    else
        v = Wv[(long)l * 65536 + f * 2048 + a * 32 + ((c - 128) >> 1)];
    g_wdup[idx] = v;
}

// ---------------- edge geometry ---------------------------------------------
__global__ void geom_kernel(const float* __restrict__ coords,
                            const int* __restrict__ eidx) {
    int e = blockIdx.x * blockDim.x + threadIdx.x;
    if (e >= EE) return;
    int snd = eidx[e];
    int rcv = eidx[EE + e];
    float dx = coords[snd * 3 + 0] - coords[rcv * 3 + 0];
    float dy = coords[snd * 3 + 1] - coords[rcv * 3 + 1];
    float dz = coords[snd * 3 + 2] - coords[rcv * 3 + 2];
    float r = sqrtf(dx * dx + dy * dy + dz * dz + 1e-12f);
    float invr = 1.0f / r;
    float sc = 1.7320508075688772f * invr;
    g_geo[e] = make_float4(r * 0.2f, sc * dx, sc * dy, sc * dz);
    g_se[e] = make_int2(snd, rcv);
}

// ---------------- node embedding -------------------------------------------
__global__ void emb_kernel(const float* __restrict__ attrs,
                           const float* __restrict__ W) {
    int gid = blockIdx.x * 256 + threadIdx.x;
    int n = gid >> 5;
    int f = gid & 31;
    float acc = 0.0f;
#pragma unroll 8
    for (int a = 0; a < 64; a++) acc += attrs[n * 64 + a] * W[a * 32 + f];
    ((float4*)g_sv)[gid] = make_float4(acc, 0.0f, 0.0f, 0.0f);
}

// ---------------- edge kernel: table lerp + message + scatter ---------------
__global__ __launch_bounds__(256) void edge_kernel(const float* __restrict__ tab) {
    int gw = (blockIdx.x * 256 + threadIdx.x) >> 5;
    int tx = threadIdx.x & 31;
    int nw = (gridDim.x * 256) >> 5;
    int per = (EE + nw - 1) / nw;
    int e0 = gw * per;
    int e1 = min(e0 + per, EE);

    const float INV = 0.17677669529663689f;   // 1/sqrt(32)
    const float4* sv4 = (const float4*)g_sv;

    for (int e = e0; e < e1; e++) {
        int2 sr = __ldg(&g_se[e]);
        float4 gy = __ldg(&g_geo[e]);

        float u = fminf(gy.x, 1.0f) * (float)(TT - 1);
        int ix = min((int)u, TT - 2);
        float fr = u - (float)ix;

        const float* tp = tab + (long)ix * 160 + tx;
        float w[5];
#pragma unroll
        for (int p = 0; p < 5; p++) {
            float a = __ldg(tp + p * 32);
            float b = __ldg(tp + 160 + p * 32);
            w[p] = fmaf(fr, b - a, a);
        }

        float4 sv = __ldg(&sv4[(long)sr.x * 32 + tx]);
        float y0 = gy.y, y1 = gy.z, y2 = gy.w;
        float sj = sv.x, vj0 = sv.y, vj1 = sv.z, vj2 = sv.w;
        float dot = vj0 * y0 + vj1 * y1 + vj2 * y2;
        float cx = vj1 * y2 - vj2 * y1;
        float cy = vj2 * y0 - vj0 * y2;
        float cz = vj0 * y1 - vj1 * y0;
        float ms  = (w[0] * sj + w[3] * dot) * INV;
        float mv0 = (w[1] * sj * y0 + w[2] * vj0 + w[4] * cx) * INV;
        float mv1 = (w[1] * sj * y1 + w[2] * vj1 + w[4] * cy) * INV;
        float mv2 = (w[1] * sj * y2 + w[2] * vj2 + w[4] * cz) * INV;
        red_v4(&g_agg[((long)sr.y * 32 + tx) * 4], ms, mv0, mv1, mv2);
    }
}

// ---------------- node update (f-split 2, pre-duplicated weights) -----------
#define NODE_SMEM_BYTES (18816 * 4)

__device__ __forceinline__ void node_issue_stage(float* dst,
        const float* __restrict__ Wd, int s, int tid) {
    const float4* src = (const float4*)(Wd + s * 3072);
    float4* d = (float4*)dst;
#pragma unroll
    for (int i = 0; i < 3; i++) cpa16(d + tid + i * 256, src + tid + i * 256);
}

__global__ __launch_bounds__(256, 3) void node_kernel(
    const float* __restrict__ attrs,
    const float* __restrict__ Ls, const float* __restrict__ Lv,
    const float* __restrict__ Wdup) {
    extern __shared__ float sm[];
    float* sW   = sm;            // 4 x 3072
    float* sAtT = sm + 12288;    // [a][n] stride 34
    float* sST  = sAtT + 2176;   // [f_local][n] stride 34 (16 rows)
    float* sVT  = sST + 544;     // [c*16+f_local][n] stride 34 (48 rows)
    float* sAgS = sVT + 1632;
    float* sAgV = sAgS + 544;

    int tid = threadIdx.x, tx = tid & 31, ty = tid >> 5;
    int tile = blockIdx.x >> 1;
    int f0 = (blockIdx.x & 1) * 16;
    int base = tile * 32;
    int nA = ty * 4;
    const float* Wd = Wdup + (long)f0 * 12288;

    node_issue_stage(sW + 0 * 3072, Wd, 0, tid); CP_COMMIT;
    node_issue_stage(sW + 1 * 3072, Wd, 1, tid); CP_COMMIT;

    const float4* sv4 = (const float4*)g_sv;
    const float4* ag4 = (const float4*)g_agg;
    for (int i = tid; i < 512; i += 256) {
        int fl = i & 15, n = i >> 4;
        float4 a = sv4[(long)(base + n) * 32 + f0 + fl];
        sST[fl * 34 + n] = a.x;
        sVT[fl * 34 + n] = a.y;
        sVT[(16 + fl) * 34 + n] = a.z;
        sVT[(32 + fl) * 34 + n] = a.w;
        float4 b = ag4[(long)(base + n) * 32 + f0 + fl];
        sAgS[fl * 34 + n] = b.x;
        sAgV[fl * 34 + n] = b.y;
        sAgV[(16 + fl) * 34 + n] = b.z;
        sAgV[(32 + fl) * 34 + n] = b.w;
    }
    for (int i = tid; i < 2048; i += 256) {
        int a = i & 63, n = i >> 6;
        sAtT[a * 34 + n] = attrs[(base + n) * 64 + a];
    }

    ULL acc0[2] = {0, 0}, acc1[2] = {0, 0}, acc2[2] = {0, 0},
        acc3[2] = {0, 0}, acc4[2] = {0, 0};

    int qi = 0;
    for (int fl = 0; fl < 16; fl++) {
        int fg = f0 + fl;
        ULL Ls02 = dup2(__ldg(&Ls[fg * 64 + tx]));
        ULL Ls12 = dup2(__ldg(&Ls[fg * 64 + 32 + tx]));
        ULL Lv02 = dup2(__ldg(&Lv[fg * 32 + tx]));

        ULL sf2[2], v02[2], v12[2], v22[2];
        if (fl == 0) __syncthreads();
#pragma unroll
        for (int P = 0; P < 2; P++) {
            int nn = nA + 2 * P;
            sf2[P] = *(const ULL*)&sST[fl * 34 + nn];
            v02[P] = *(const ULL*)&sVT[fl * 34 + nn];
            v12[P] = *(const ULL*)&sVT[(16 + fl) * 34 + nn];
            v22[P] = *(const ULL*)&sVT[(32 + fl) * 34 + nn];
            ULL ag = *(const ULL*)&sAgS[fl * 34 + nn];
            fma2(acc0[P], ag, Ls02);
            fma2(acc1[P], ag, Ls12);
            fma2(acc2[P], *(const ULL*)&sAgV[fl * 34 + nn], Lv02);
            fma2(acc3[P], *(const ULL*)&sAgV[(16 + fl) * 34 + nn], Lv02);
            fma2(acc4[P], *(const ULL*)&sAgV[(32 + fl) * 34 + nn], Lv02);
        }

#pragma unroll 1
        for (int q = 0; q < 4; q++, qi++) {
            if (qi + 2 < 64)
                node_issue_stage(sW + ((qi + 2) & 3) * 3072, Wd, qi + 2, tid);
            CP_COMMIT;
            asm volatile("cp.async.wait_group 2;");
            __syncthreads();

            const float* sWq = sW + (qi & 3) * 3072;
#pragma unroll 4
            for (int aa = 0; aa < 16; aa++) {
                int ag_ = (q * 16 + aa);
                ULL at20 = *(const ULL*)&sAtT[ag_ * 34 + nA];
                ULL at21 = *(const ULL*)&sAtT[ag_ * 34 + nA + 2];
                ULL W02  = *(const ULL*)&sWq[aa * 192 + tx * 2];
                ULL W12  = *(const ULL*)&sWq[aa * 192 + 64 + tx * 2];
                ULL Wv02 = *(const ULL*)&sWq[aa * 192 + 128 + tx * 2];
                {
                    ULL us2 = mul2(sf2[0], at20);
                    ULL tv2 = mul2(at20, Wv02);
                    fma2(acc0[0], us2, W02);
                    fma2(acc1[0], us2, W12);
                    fma2(acc2[0], v02[0], tv2);
                    fma2(acc3[0], v12[0], tv2);
                    fma2(acc4[0], v22[0], tv2);
                }
                {
                    ULL us2 = mul2(sf2[1], at21);
                    ULL tv2 = mul2(at21, Wv02);
                    fma2(acc0[1], us2, W02);
                    fma2(acc1[1], us2, W12);
                    fma2(acc2[1], v02[1], tv2);
                    fma2(acc3[1], v12[1], tv2);
                    fma2(acc4[1], v22[1], tv2);
                }
            }
        }
    }

#pragma unroll
    for (int P = 0; P < 2; P++) {
        float ft[2], gt[2], a2[2], a3[2], a4[2];
        upk2(acc0[P], ft[0], ft[1]);
        upk2(acc1[P], gt[0], gt[1]);
        upk2(acc2[P], a2[0], a2[1]);
        upk2(acc3[P], a3[0], a3[1]);
        upk2(acc4[P], a4[0], a4[1]);
#pragma unroll
        for (int h = 0; h < 2; h++) {
            int gn = base + nA + 2 * P + h;
            float* p = g_pre + (long)gn * 160 + tx;
            atomicAdd(p, ft[h]);
            atomicAdd(p + 32, gt[h]);
            atomicAdd(p + 64, a2[h]);
            atomicAdd(p + 96, a3[h]);
            atomicAdd(p + 128, a4[h]);
        }
    }
}

// ---------------- node epilogue ---------------------------------------------
__global__ void epi_kernel() {
    int idx = blockIdx.x * 256 + threadIdx.x;
    if (idx >= NN * 32) return;
    int n = idx >> 5, tx = idx & 31;
    const float* p = g_pre + (long)n * 160 + tx;
    float ft = p[0], gt = p[32], a2 = p[64], a3 = p[96], a4 = p[128];
    float4 o = ((float4*)g_sv)[idx];
    float sg = fsig(gt);
    float s_new = fsilu(ft) + o.x;
    ((float4*)g_sv)[idx] =
        make_float4(s_new, a2 * sg + o.y, a3 * sg + o.z, a4 * sg + o.w);
}

// ---------------- output assembly -------------------------------------------
__global__ void out_kernel(float* __restrict__ out) {
    int idx = blockIdx.x * 256 + threadIdx.x;
    if (idx >= NN * 128) return;
    int n = idx >> 7, j = idx & 127;
    float val;
    if (j < 32) {
        val = g_sv[((long)n * 32 + j) * 4];
    } else {
        int t = j - 32;
        int f = t / 3;
        int c = t - 3 * f;
        val = g_sv[((long)n * 32 + f) * 4 + 1 + c];
    }
    out[idx] = val;
}

// ---------------- launch -----------------------------------------------------
extern "C" void kernel_launch(void* const* d_in, const int* in_sizes, int n_in,
                              void* d_out, int out_size) {
    const float* attrs  = (const float*)d_in[0];
    const float* coords = (const float*)d_in[1];
    const int*   eidx   = (const int*)d_in[2];
    const float* embW   = (const float*)d_in[3];
    const float* rW1    = (const float*)d_in[4];
    const float* rb1    = (const float*)d_in[5];
    const float* rW2    = (const float*)d_in[6];
    const float* Ls     = (const float*)d_in[7];
    const float* Lv     = (const float*)d_in[8];
    const float* Ws     = (const float*)d_in[9];
    const float* Wv     = (const float*)d_in[10];
    float* out = (float*)d_out;

    cudaFuncSetAttribute(node_kernel,
                         cudaFuncAttributeMaxDynamicSharedMemorySize,
                         NODE_SMEM_BYTES);

    void* pagg = nullptr;
    void* ppre = nullptr;
    void* pwd = nullptr;
    void* ptab = nullptr;
    cudaGetSymbolAddress(&pagg, g_agg);
    cudaGetSymbolAddress(&ppre, g_pre);
    cudaGetSymbolAddress(&pwd, g_wdup);
    cudaGetSymbolAddress(&ptab, g_tab);

    tab_kernel<<<2 * TT, 160>>>(rW1, rb1, rW2);
    dupw_kernel<<<3072, 256>>>(Ws, Wv);
    geom_kernel<<<(EE + 255) / 256, 256>>>(coords, eidx);
    emb_kernel<<<NN * 32 / 256, 256>>>(attrs, embW);

    for (int l = 0; l < 2; l++) {
        cudaMemsetAsync(pagg, 0, NN * 128 * sizeof(float));
        cudaMemsetAsync(ppre, 0, NN * 160 * sizeof(float));
        edge_kernel<<<1184, 256>>>((const float*)ptab + (long)l * TT * 160);
        node_kernel<<<1250, 256, NODE_SMEM_BYTES>>>(
            attrs, Ls + l * 2048, Lv + l * 1024,
            (const float*)pwd + (long)l * 393216);
        epi_kernel<<<(NN * 32 + 255) / 256, 256>>>();
    }
    out_kernel<<<(NN * 128 + 255) / 256, 256>>>(out);
}

// round 8
// speedup vs baseline: 2.2493x; 1.0429x over previous
#include <cuda_runtime.h>
#include <math.h>

#define NN 20000
#define EE 640000
#define TT 4096

typedef unsigned long long ULL;

// ---------------- packed f32x2 helpers -------------------------------------
__device__ __forceinline__ ULL pk2(float lo, float hi) {
    ULL r; asm("mov.b64 %0,{%1,%2};" : "=l"(r) : "f"(lo), "f"(hi)); return r;
}
__device__ __forceinline__ ULL dup2(float v) { return pk2(v, v); }
__device__ __forceinline__ void upk2(ULL v, float& lo, float& hi) {
    asm("mov.b64 {%0,%1},%2;" : "=f"(lo), "=f"(hi) : "l"(v));
}
__device__ __forceinline__ void fma2(ULL& d, ULL a, ULL b) {
    asm("fma.rn.f32x2 %0,%1,%2,%0;" : "+l"(d) : "l"(a), "l"(b));
}
__device__ __forceinline__ ULL mul2(ULL a, ULL b) {
    ULL d; asm("mul.rn.f32x2 %0,%1,%2;" : "=l"(d) : "l"(a), "l"(b)); return d;
}

// ---------------- cp.async helpers ------------------------------------------
__device__ __forceinline__ void cpa16(void* smem_dst, const void* gsrc) {
    unsigned s = (unsigned)__cvta_generic_to_shared(smem_dst);
    asm volatile("cp.async.cg.shared.global [%0],[%1],16;" :: "r"(s), "l"(gsrc));
}
#define CP_COMMIT asm volatile("cp.async.commit_group;")

// ---------------- vector RED ------------------------------------------------
__device__ __forceinline__ void red_v4(float* p, float a, float b, float c, float d) {
    asm volatile("red.global.add.v4.f32 [%0],{%1,%2,%3,%4};"
                 :: "l"(p), "f"(a), "f"(b), "f"(c), "f"(d) : "memory");
}

__device__ __forceinline__ float fsilu(float x) {
    return x * __fdividef(1.0f, 1.0f + __expf(-x));
}
__device__ __forceinline__ float fsig(float x) {
    return __fdividef(1.0f, 1.0f + __expf(-x));
}

// ---------------- scratch ----------------------------------------------------
__device__ float4 g_geo[EE];        // {x, Y0, Y1, Y2}
__device__ int2   g_se[EE];         // {snd, rcv}
__device__ float  g_sv[NN * 128];   // [n][f]{s,v0,v1,v2} packed float4
__device__ float  g_agg[NN * 128];  // same packing
__device__ float  g_pre[NN * 160];  // [n][p][32]
__device__ float  g_wdup[786432];   // duplicated node weights, 2 layers
__device__ float  g_tab[2 * TT * 160];       // radial lookup values
__device__ float2 g_tab2[2 * TT * 160];      // {value, slope} pairs

// ---------------- radial table build (runs once, 2*4096 points) -------------
__global__ void tab_kernel(const float* __restrict__ rW1,
                           const float* __restrict__ rb1,
                           const float* __restrict__ rW2) {
    int l = blockIdx.x >> 12;
    int i = blockIdx.x & (TT - 1);
    int tid = threadIdx.x;       // 160 threads
    __shared__ float H[64];
    float x = (float)i * (1.0f / (float)(TT - 1));
    float xe = fmaxf(x, 1e-7f);
    if (tid < 64) {
        float r = 5.0f * xe;
        float x3 = xe * xe * xe;
        float x6 = x3 * x3;
        float x7 = x6 * xe;
        float x8 = x7 * xe;
        float fc = (xe < 1.0f) ? (1.0f - 28.0f * x6 + 48.0f * x7 - 21.0f * x8) : 0.0f;
        float c = 0.6324555320336759f * fc / r;
        float acc = rb1[l * 64 + tid];
#pragma unroll
        for (int n = 1; n <= 8; n++) {
            float ef = c * sinf((float)n * 3.14159265358979323846f * xe);
            acc += ef * rW1[l * 512 + (n - 1) * 64 + tid];
        }
        H[tid] = acc / (1.0f + expf(-acc));
    }
    __syncthreads();
    float out = 0.0f;
#pragma unroll 8
    for (int k = 0; k < 64; k++)
        out += H[k] * rW2[l * 10240 + k * 160 + tid];
    g_tab[((long)l * TT + i) * 160 + tid] = out;
}

// ---------------- value/slope pairing (runs once) ----------------------------
__global__ void pair_kernel() {
    int idx = blockIdx.x * 256 + threadIdx.x;
    if (idx >= 2 * TT * 160) return;
    int i = (idx / 160) & (TT - 1);
    float v = g_tab[idx];
    float vn = (i < TT - 1) ? g_tab[idx + 160] : v;
    g_tab2[idx] = make_float2(v, vn - v);
}

// ---------------- weight duplication (runs once) ----------------------------
__global__ void dupw_kernel(const float* __restrict__ Ws,
                            const float* __restrict__ Wv) {
    int idx = blockIdx.x * 256 + threadIdx.x;   // < 786432
    int l = idx / 393216;
    int rem = idx - l * 393216;
    int f = rem / 12288;
    int a = (rem / 192) % 64;
    int c = rem % 192;
    float v;
    if (c < 128)
        v = Ws[(long)l * 131072 + f * 4096 + a * 64 + (c >> 1)];
    else
        v = Wv[(long)l * 65536 + f * 2048 + a * 32 + ((c - 128) >> 1)];
    g_wdup[idx] = v;
}

// ---------------- edge geometry ---------------------------------------------
__global__ void geom_kernel(const float* __restrict__ coords,
                            const int* __restrict__ eidx) {
    int e = blockIdx.x * blockDim.x + threadIdx.x;
    if (e >= EE) return;
    int snd = eidx[e];
    int rcv = eidx[EE + e];
    float dx = coords[snd * 3 + 0] - coords[rcv * 3 + 0];
    float dy = coords[snd * 3 + 1] - coords[rcv * 3 + 1];
    float dz = coords[snd * 3 + 2] - coords[rcv * 3 + 2];
    float r = sqrtf(dx * dx + dy * dy + dz * dz + 1e-12f);
    float invr = 1.0f / r;
    float sc = 1.7320508075688772f * invr;
    g_geo[e] = make_float4(r * 0.2f, sc * dx, sc * dy, sc * dz);
    g_se[e] = make_int2(snd, rcv);
}

// ---------------- node embedding -------------------------------------------
__global__ void emb_kernel(const float* __restrict__ attrs,
                           const float* __restrict__ W) {
    int gid = blockIdx.x * 256 + threadIdx.x;
    int n = gid >> 5;
    int f = gid & 31;
    float acc = 0.0f;
#pragma unroll 8
    for (int a = 0; a < 64; a++) acc += attrs[n * 64 + a] * W[a * 32 + f];
    ((float4*)g_sv)[gid] = make_float4(acc, 0.0f, 0.0f, 0.0f);
}

// ---------------- edge kernel: slope-table lerp + message + scatter ---------
__global__ __launch_bounds__(256) void edge_kernel(const float2* __restrict__ tab2) {
    int gw = (blockIdx.x * 256 + threadIdx.x) >> 5;
    int tx = threadIdx.x & 31;
    int nw = (gridDim.x * 256) >> 5;
    int per = (EE + nw - 1) / nw;
    int e0 = gw * per;
    int e1 = min(e0 + per, EE);

    const float INV = 0.17677669529663689f;   // 1/sqrt(32)
    const float4* sv4 = (const float4*)g_sv;

    for (int e = e0; e < e1; e++) {
        int2 sr = __ldg(&g_se[e]);
        float4 gy = __ldg(&g_geo[e]);

        float u = fminf(gy.x, 1.0f) * (float)(TT - 1);
        int ix = min((int)u, TT - 2);
        float fr = u - (float)ix;

        const float2* tp = tab2 + (long)ix * 160 + tx;
        float w[5];
#pragma unroll
        for (int p = 0; p < 5; p++) {
            float2 ab = __ldg(tp + p * 32);
            w[p] = fmaf(fr, ab.y, ab.x);
        }

        float4 sv = __ldg(&sv4[(long)sr.x * 32 + tx]);
        float y0 = gy.y, y1 = gy.z, y2 = gy.w;
        float sj = sv.x, vj0 = sv.y, vj1 = sv.z, vj2 = sv.w;
        float dot = vj0 * y0 + vj1 * y1 + vj2 * y2;
        float cx = vj1 * y2 - vj2 * y1;
        float cy = vj2 * y0 - vj0 * y2;
        float cz = vj0 * y1 - vj1 * y0;
        float ms  = (w[0] * sj + w[3] * dot) * INV;
        float mv0 = (w[1] * sj * y0 + w[2] * vj0 + w[4] * cx) * INV;
        float mv1 = (w[1] * sj * y1 + w[2] * vj1 + w[4] * cy) * INV;
        float mv2 = (w[1] * sj * y2 + w[2] * vj2 + w[4] * cz) * INV;
        red_v4(&g_agg[((long)sr.y * 32 + tx) * 4], ms, mv0, mv1, mv2);
    }
}

// ---------------- node update (64-node tiles, f-split 4) --------------------
// smem floats: ring 4x3072=12288 | AtT 64x66=4224 | ST 8x66=528 | VT 24x66=1584 |
//              AgS 528 | AgV 1584 -> 20736 floats = 82944 B (2 CTAs/SM)
#define NODE_SMEM_BYTES (20736 * 4)
#define NTILES 313   // ceil(20000/64)

__device__ __forceinline__ void node_issue_stage(float* ring,
        const float* __restrict__ Wd, int s, int tid) {
    float* dst = ring + (s & 3) * 3072;
    const float4* src = (const float4*)(Wd + (s >> 2) * 12288 + (s & 3) * 3072);
    float4* d = (float4*)dst;
#pragma unroll
    for (int i = 0; i < 3; i++) cpa16(d + tid + i * 256, src + tid + i * 256);
}

__global__ __launch_bounds__(256, 2) void node_kernel(
    const float* __restrict__ attrs,
    const float* __restrict__ Ls, const float* __restrict__ Lv,
    const float* __restrict__ Wdup) {
    extern __shared__ float sm[];
    float* sW   = sm;            // 4 x 3072 ring
    float* sAtT = sm + 12288;    // [a][n] stride 66
    float* sST  = sAtT + 4224;   // [f_local][n] stride 66 (8 rows)
    float* sVT  = sST + 528;     // [c*8+f_local][n] stride 66 (24 rows)
    float* sAgS = sVT + 1584;
    float* sAgV = sAgS + 528;

    int tid = threadIdx.x, tx = tid & 31, ty = tid >> 5;
    int tile = blockIdx.x >> 2;
    int F0 = (blockIdx.x & 3) * 8;
    int base = tile * 64;
    int nA = ty * 8;
    const float* Wd = Wdup + (long)F0 * 12288;

    node_issue_stage(sW, Wd, 0, tid); CP_COMMIT;
    node_issue_stage(sW, Wd, 1, tid); CP_COMMIT;

    const float4* sv4 = (const float4*)g_sv;
    const float4* ag4 = (const float4*)g_agg;
    for (int i = tid; i < 512; i += 256) {
        int fl = i & 7, n = i >> 3;
        int gn = base + n;
        float4 a = (gn < NN) ? sv4[(long)gn * 32 + F0 + fl]
                             : make_float4(0.f, 0.f, 0.f, 0.f);
        float4 b = (gn < NN) ? ag4[(long)gn * 32 + F0 + fl]
                             : make_float4(0.f, 0.f, 0.f, 0.f);
        sST[fl * 66 + n] = a.x;
        sVT[fl * 66 + n] = a.y;
        sVT[(8 + fl) * 66 + n] = a.z;
        sVT[(16 + fl) * 66 + n] = a.w;
        sAgS[fl * 66 + n] = b.x;
        sAgV[fl * 66 + n] = b.y;
        sAgV[(8 + fl) * 66 + n] = b.z;
        sAgV[(16 + fl) * 66 + n] = b.w;
    }
    for (int i = tid; i < 4096; i += 256) {
        int a = i & 63, n = i >> 6;
        int gn = base + n;
        sAtT[a * 66 + n] = (gn < NN) ? attrs[(long)gn * 64 + a] : 0.0f;
    }

    ULL acc0[4] = {0,0,0,0}, acc1[4] = {0,0,0,0}, acc2[4] = {0,0,0,0},
        acc3[4] = {0,0,0,0}, acc4[4] = {0,0,0,0};

    int qi = 0;
    for (int fl = 0; fl < 8; fl++) {
        int fg = F0 + fl;
        ULL Ls02 = dup2(__ldg(&Ls[fg * 64 + tx]));
        ULL Ls12 = dup2(__ldg(&Ls[fg * 64 + 32 + tx]));
        ULL Lv02 = dup2(__ldg(&Lv[fg * 32 + tx]));

        if (fl == 0) __syncthreads();   // node arrays ready

        ULL sf2[4], v02[4], v12[4], v22[4];
#pragma unroll
        for (int P = 0; P < 4; P++) {
            int nn = nA + 2 * P;
            sf2[P] = *(const ULL*)&sST[fl * 66 + nn];
            v02[P] = *(const ULL*)&sVT[fl * 66 + nn];
            v12[P] = *(const ULL*)&sVT[(8 + fl) * 66 + nn];
            v22[P] = *(const ULL*)&sVT[(16 + fl) * 66 + nn];
            ULL ag = *(const ULL*)&sAgS[fl * 66 + nn];
            fma2(acc0[P], ag, Ls02);
            fma2(acc1[P], ag, Ls12);
            fma2(acc2[P], *(const ULL*)&sAgV[fl * 66 + nn], Lv02);
            fma2(acc3[P], *(const ULL*)&sAgV[(8 + fl) * 66 + nn], Lv02);
            fma2(acc4[P], *(const ULL*)&sAgV[(16 + fl) * 66 + nn], Lv02);
        }

#pragma unroll 1
        for (int q = 0; q < 4; q++, qi++) {
            if (qi + 2 < 32) node_issue_stage(sW, Wd, qi + 2, tid);
            CP_COMMIT;
            asm volatile("cp.async.wait_group 2;");
            __syncthreads();

            const float* sWq = sW + (qi & 3) * 3072;
#pragma unroll 2
            for (int aa = 0; aa < 16; aa++) {
                int ag_ = q * 16 + aa;
                ULL W02  = *(const ULL*)&sWq[aa * 192 + tx * 2];
                ULL W12  = *(const ULL*)&sWq[aa * 192 + 64 + tx * 2];
                ULL Wv02 = *(const ULL*)&sWq[aa * 192 + 128 + tx * 2];
#pragma unroll
                for (int P = 0; P < 4; P++) {
                    ULL at2 = *(const ULL*)&sAtT[ag_ * 66 + nA + 2 * P];
                    ULL us2 = mul2(sf2[P], at2);
                    ULL tv2 = mul2(at2, Wv02);
                    fma2(acc0[P], us2, W02);
                    fma2(acc1[P], us2, W12);
                    fma2(acc2[P], v02[P], tv2);
                    fma2(acc3[P], v12[P], tv2);
                    fma2(acc4[P], v22[P], tv2);
                }
            }
        }
    }

    // epilogue: RED partial sums into g_pre
#pragma unroll
    for (int P = 0; P < 4; P++) {
        float ft[2], gt[2], a2[2], a3[2], a4[2];
        upk2(acc0[P], ft[0], ft[1]);
        upk2(acc1[P], gt[0], gt[1]);
        upk2(acc2[P], a2[0], a2[1]);
        upk2(acc3[P], a3[0], a3[1]);
        upk2(acc4[P], a4[0], a4[1]);
#pragma unroll
        for (int h = 0; h < 2; h++) {
            int gn = base + nA + 2 * P + h;
            if (gn < NN) {
                float* p = g_pre + (long)gn * 160 + tx;
                atomicAdd(p, ft[h]);
                atomicAdd(p + 32, gt[h]);
                atomicAdd(p + 64, a2[h]);
                atomicAdd(p + 96, a3[h]);
                atomicAdd(p + 128, a4[h]);
            }
        }
    }
}

// ---------------- node epilogue ---------------------------------------------
__global__ void epi_kernel() {
    int idx = blockIdx.x * 256 + threadIdx.x;
    if (idx >= NN * 32) return;
    int n = idx >> 5, tx = idx & 31;
    const float* p = g_pre + (long)n * 160 + tx;
    float ft = p[0], gt = p[32], a2 = p[64], a3 = p[96], a4 = p[128];
    float4 o = ((float4*)g_sv)[idx];
    float sg = fsig(gt);
    float s_new = fsilu(ft) + o.x;
    ((float4*)g_sv)[idx] =
        make_float4(s_new, a2 * sg + o.y, a3 * sg + o.z, a4 * sg + o.w);
}

// ---------------- output assembly -------------------------------------------
__global__ void out_kernel(float* __restrict__ out) {
    int idx = blockIdx.x * 256 + threadIdx.x;
    if (idx >= NN * 128) return;
    int n = idx >> 7, j = idx & 127;
    float val;
    if (j < 32) {
        val = g_sv[((long)n * 32 + j) * 4];
    } else {
        int t = j - 32;
        int f = t / 3;
        int c = t - 3 * f;
        val = g_sv[((long)n * 32 + f) * 4 + 1 + c];
    }
    out[idx] = val;
}

// ---------------- launch -----------------------------------------------------
extern "C" void kernel_launch(void* const* d_in, const int* in_sizes, int n_in,
                              void* d_out, int out_size) {
    const float* attrs  = (const float*)d_in[0];
    const float* coords = (const float*)d_in[1];
    const int*   eidx   = (const int*)d_in[2];
    const float* embW   = (const float*)d_in[3];
    const float* rW1    = (const float*)d_in[4];
    const float* rb1    = (const float*)d_in[5];
    const float* rW2    = (const float*)d_in[6];
    const float* Ls     = (const float*)d_in[7];
    const float* Lv     = (const float*)d_in[8];
    const float* Ws     = (const float*)d_in[9];
    const float* Wv     = (const float*)d_in[10];
    float* out = (float*)d_out;

    cudaFuncSetAttribute(node_kernel,
                         cudaFuncAttributeMaxDynamicSharedMemorySize,
                         NODE_SMEM_BYTES);

    void *pagg = nullptr, *ppre = nullptr, *pwd = nullptr, *ptab2 = nullptr;
    cudaGetSymbolAddress(&pagg, g_agg);
    cudaGetSymbolAddress(&ppre, g_pre);
    cudaGetSymbolAddress(&pwd, g_wdup);
    cudaGetSymbolAddress(&ptab2, g_tab2);

    tab_kernel<<<2 * TT, 160>>>(rW1, rb1, rW2);
    pair_kernel<<<(2 * TT * 160 + 255) / 256, 256>>>();
    dupw_kernel<<<3072, 256>>>(Ws, Wv);
    geom_kernel<<<(EE + 255) / 256, 256>>>(coords, eidx);
    emb_kernel<<<NN * 32 / 256, 256>>>(attrs, embW);

    for (int l = 0; l < 2; l++) {
        cudaMemsetAsync(pagg, 0, NN * 128 * sizeof(float));
        cudaMemsetAsync(ppre, 0, NN * 160 * sizeof(float));
        edge_kernel<<<1184, 256>>>((const float2*)ptab2 + (long)l * TT * 160);
        node_kernel<<<NTILES * 4, 256, NODE_SMEM_BYTES>>>(
            attrs, Ls + l * 2048, Lv + l * 1024,
            (const float*)pwd + (long)l * 393216);
        epi_kernel<<<(NN * 32 + 255) / 256, 256>>>();
    }
    out_kernel<<<(NN * 128 + 255) / 256, 256>>>(out);
}

// round 9
// speedup vs baseline: 3.0784x; 1.3686x over previous
#include <cuda_runtime.h>
#include <math.h>

#define NN 20000
#define EE 640000
#define TT 4096

typedef unsigned long long ULL;

// ---------------- packed f32x2 helpers -------------------------------------
__device__ __forceinline__ ULL pk2(float lo, float hi) {
    ULL r; asm("mov.b64 %0,{%1,%2};" : "=l"(r) : "f"(lo), "f"(hi)); return r;
}
__device__ __forceinline__ ULL dup2(float v) { return pk2(v, v); }
__device__ __forceinline__ void upk2(ULL v, float& lo, float& hi) {
    asm("mov.b64 {%0,%1},%2;" : "=f"(lo), "=f"(hi) : "l"(v));
}
__device__ __forceinline__ void fma2(ULL& d, ULL a, ULL b) {
    asm("fma.rn.f32x2 %0,%1,%2,%0;" : "+l"(d) : "l"(a), "l"(b));
}
__device__ __forceinline__ ULL mul2(ULL a, ULL b) {
    ULL d; asm("mul.rn.f32x2 %0,%1,%2;" : "=l"(d) : "l"(a), "l"(b)); return d;
}

// ---------------- cp.async helpers ------------------------------------------
__device__ __forceinline__ void cpa16(void* smem_dst, const void* gsrc) {
    unsigned s = (unsigned)__cvta_generic_to_shared(smem_dst);
    asm volatile("cp.async.cg.shared.global [%0],[%1],16;" :: "r"(s), "l"(gsrc));
}
#define CP_COMMIT asm volatile("cp.async.commit_group;")

// ---------------- vector RED ------------------------------------------------
__device__ __forceinline__ void red_v4(float* p, float a, float b, float c, float d) {
    asm volatile("red.global.add.v4.f32 [%0],{%1,%2,%3,%4};"
                 :: "l"(p), "f"(a), "f"(b), "f"(c), "f"(d) : "memory");
}

__device__ __forceinline__ float fsilu(float x) {
    return x * __fdividef(1.0f, 1.0f + __expf(-x));
}
__device__ __forceinline__ float fsig(float x) {
    return __fdividef(1.0f, 1.0f + __expf(-x));
}

// ---------------- scratch ----------------------------------------------------
__device__ float4 g_geo[EE];        // {x, Y0, Y1, Y2}
__device__ int2   g_se[EE];         // {snd, rcv}
__device__ float  g_sv[NN * 128];   // [n][f]{s,v0,v1,v2} packed float4
__device__ float  g_agg[NN * 128];  // same packing
__device__ float  g_pre[NN * 160];  // [n][p][32]
__device__ float  g_wdup[786432];   // duplicated node weights, 2 layers
__device__ float  g_tab[2 * TT * 160];       // radial lookup values
__device__ float2 g_tab2[2 * TT * 160];      // {value, slope} pairs

// ---------------- radial table build (runs once, 2*4096 points) -------------
__global__ void tab_kernel(const float* __restrict__ rW1,
                           const float* __restrict__ rb1,
                           const float* __restrict__ rW2) {
    int l = blockIdx.x >> 12;
    int i = blockIdx.x & (TT - 1);
    int tid = threadIdx.x;       // 160 threads
    __shared__ float H[64];
    float x = (float)i * (1.0f / (float)(TT - 1));
    float xe = fmaxf(x, 1e-7f);
    if (tid < 64) {
        float r = 5.0f * xe;
        float x3 = xe * xe * xe;
        float x6 = x3 * x3;
        float x7 = x6 * xe;
        float x8 = x7 * xe;
        float fc = (xe < 1.0f) ? (1.0f - 28.0f * x6 + 48.0f * x7 - 21.0f * x8) : 0.0f;
        float c = 0.6324555320336759f * fc / r;
        float acc = rb1[l * 64 + tid];
#pragma unroll
        for (int n = 1; n <= 8; n++) {
            float ef = c * sinf((float)n * 3.14159265358979323846f * xe);
            acc += ef * rW1[l * 512 + (n - 1) * 64 + tid];
        }
        H[tid] = acc / (1.0f + expf(-acc));
    }
    __syncthreads();
    float out = 0.0f;
#pragma unroll 8
    for (int k = 0; k < 64; k++)
        out += H[k] * rW2[l * 10240 + k * 160 + tid];
    g_tab[((long)l * TT + i) * 160 + tid] = out;
}

// ---------------- value/slope pairing (runs once) ----------------------------
__global__ void pair_kernel() {
    int idx = blockIdx.x * 256 + threadIdx.x;
    if (idx >= 2 * TT * 160) return;
    int i = (idx / 160) & (TT - 1);
    float v = g_tab[idx];
    float vn = (i < TT - 1) ? g_tab[idx + 160] : v;
    g_tab2[idx] = make_float2(v, vn - v);
}

// ---------------- weight duplication (runs once) ----------------------------
__global__ void dupw_kernel(const float* __restrict__ Ws,
                            const float* __restrict__ Wv) {
    int idx = blockIdx.x * 256 + threadIdx.x;   // < 786432
    int l = idx / 393216;
    int rem = idx - l * 393216;
    int f = rem / 12288;
    int a = (rem / 192) % 64;
    int c = rem % 192;
    float v;
    if (c < 128)
        v = Ws[(long)l * 131072 + f * 4096 + a * 64 + (c >> 1)];
    else
        v = Wv[(long)l * 65536 + f * 2048 + a * 32 + ((c - 128) >> 1)];
    g_wdup[idx] = v;
}

// ---------------- edge geometry ---------------------------------------------
__global__ void geom_kernel(const float* __restrict__ coords,
                            const int* __restrict__ eidx) {
    int e = blockIdx.x * blockDim.x + threadIdx.x;
    if (e >= EE) return;
    int snd = eidx[e];
    int rcv = eidx[EE + e];
    float dx = coords[snd * 3 + 0] - coords[rcv * 3 + 0];
    float dy = coords[snd * 3 + 1] - coords[rcv * 3 + 1];
    float dz = coords[snd * 3 + 2] - coords[rcv * 3 + 2];
    float r = sqrtf(dx * dx + dy * dy + dz * dz + 1e-12f);
    float invr = 1.0f / r;
    float sc = 1.7320508075688772f * invr;
    g_geo[e] = make_float4(r * 0.2f, sc * dx, sc * dy, sc * dz);
    g_se[e] = make_int2(snd, rcv);
}

// ---------------- node embedding -------------------------------------------
__global__ void emb_kernel(const float* __restrict__ attrs,
                           const float* __restrict__ W) {
    int gid = blockIdx.x * 256 + threadIdx.x;
    int n = gid >> 5;
    int f = gid & 31;
    float acc = 0.0f;
#pragma unroll 8
    for (int a = 0; a < 64; a++) acc += attrs[n * 64 + a] * W[a * 32 + f];
    ((float4*)g_sv)[gid] = make_float4(acc, 0.0f, 0.0f, 0.0f);
}

// ---------------- edge kernel: slope-table lerp + message + scatter ---------
__global__ __launch_bounds__(256) void edge_kernel(const float2* __restrict__ tab2) {
    int gw = (blockIdx.x * 256 + threadIdx.x) >> 5;
    int tx = threadIdx.x & 31;
    int nw = (gridDim.x * 256) >> 5;
    int per = (EE + nw - 1) / nw;
    int e0 = gw * per;
    int e1 = min(e0 + per, EE);

    const float INV = 0.17677669529663689f;   // 1/sqrt(32)
    const float4* sv4 = (const float4*)g_sv;

    for (int e = e0; e < e1; e++) {
        int2 sr = __ldg(&g_se[e]);
        float4 gy = __ldg(&g_geo[e]);

        float u = fminf(gy.x, 1.0f) * (float)(TT - 1);
        int ix = min((int)u, TT - 2);
        float fr = u - (float)ix;

        const float2* tp = tab2 + (long)ix * 160 + tx;
        float w[5];
#pragma unroll
        for (int p = 0; p < 5; p++) {
            float2 ab = __ldg(tp + p * 32);
            w[p] = fmaf(fr, ab.y, ab.x);
        }

        float4 sv = __ldg(&sv4[(long)sr.x * 32 + tx]);
        float y0 = gy.y, y1 = gy.z, y2 = gy.w;
        float sj = sv.x, vj0 = sv.y, vj1 = sv.z, vj2 = sv.w;
        float dot = vj0 * y0 + vj1 * y1 + vj2 * y2;
        float cx = vj1 * y2 - vj2 * y1;
        float cy = vj2 * y0 - vj0 * y2;
        float cz = vj0 * y1 - vj1 * y0;
        float ms  = (w[0] * sj + w[3] * dot) * INV;
        float mv0 = (w[1] * sj * y0 + w[2] * vj0 + w[4] * cx) * INV;
        float mv1 = (w[1] * sj * y1 + w[2] * vj1 + w[4] * cy) * INV;
        float mv2 = (w[1] * sj * y2 + w[2] * vj2 + w[4] * cz) * INV;
        red_v4(&g_agg[((long)sr.y * 32 + tx) * 4], ms, mv0, mv1, mv2);
    }
}

// ---------------- node update (64-node tiles, f-split 4, a-first factoring) -
// smem floats: ring 4x3072=12288 | AtT 64x68=4352 | ST 8x66=528 | VT 24x66=1584 |
//              AgS 528 | AgV 1584 -> 20864 floats = 83456 B (2 CTAs/SM)
#define NODE_SMEM_BYTES (20864 * 4)
#define NTILES 313   // ceil(20000/64)

__device__ __forceinline__ void node_issue_stage(float* ring,
        const float* __restrict__ Wd, int s, int tid) {
    float* dst = ring + (s & 3) * 3072;
    const float4* src = (const float4*)(Wd + (s >> 2) * 12288 + (s & 3) * 3072);
    float4* d = (float4*)dst;
#pragma unroll
    for (int i = 0; i < 3; i++) cpa16(d + tid + i * 256, src + tid + i * 256);
}

__global__ __launch_bounds__(256, 2) void node_kernel(
    const float* __restrict__ attrs,
    const float* __restrict__ Ls, const float* __restrict__ Lv,
    const float* __restrict__ Wdup) {
    extern __shared__ float sm[];
    float* sW   = sm;            // 4 x 3072 ring
    float* sAtT = sm + 12288;    // [a][n] stride 68 (16B aligned rows)
    float* sST  = sAtT + 4352;   // [f_local][n] stride 66 (8 rows)
    float* sVT  = sST + 528;     // [c*8+f_local][n] stride 66 (24 rows)
    float* sAgS = sVT + 1584;
    float* sAgV = sAgS + 528;

    int tid = threadIdx.x, tx = tid & 31, ty = tid >> 5;
    int tile = blockIdx.x >> 2;
    int F0 = (blockIdx.x & 3) * 8;
    int base = tile * 64;
    int nA = ty * 8;
    const float* Wd = Wdup + (long)F0 * 12288;

    node_issue_stage(sW, Wd, 0, tid); CP_COMMIT;
    node_issue_stage(sW, Wd, 1, tid); CP_COMMIT;

    const float4* sv4 = (const float4*)g_sv;
    const float4* ag4 = (const float4*)g_agg;
    for (int i = tid; i < 512; i += 256) {
        int fl = i & 7, n = i >> 3;
        int gn = base + n;
        float4 a = (gn < NN) ? sv4[(long)gn * 32 + F0 + fl]
                             : make_float4(0.f, 0.f, 0.f, 0.f);
        float4 b = (gn < NN) ? ag4[(long)gn * 32 + F0 + fl]
                             : make_float4(0.f, 0.f, 0.f, 0.f);
        sST[fl * 66 + n] = a.x;
        sVT[fl * 66 + n] = a.y;
        sVT[(8 + fl) * 66 + n] = a.z;
        sVT[(16 + fl) * 66 + n] = a.w;
        sAgS[fl * 66 + n] = b.x;
        sAgV[fl * 66 + n] = b.y;
        sAgV[(8 + fl) * 66 + n] = b.z;
        sAgV[(16 + fl) * 66 + n] = b.w;
    }
    for (int i = tid; i < 4096; i += 256) {
        int a = i & 63, n = i >> 6;
        int gn = base + n;
        sAtT[a * 68 + n] = (gn < NN) ? attrs[(long)gn * 64 + a] : 0.0f;
    }

    ULL acc0[4] = {0,0,0,0}, acc1[4] = {0,0,0,0}, acc2[4] = {0,0,0,0},
        acc3[4] = {0,0,0,0}, acc4[4] = {0,0,0,0};

    int qi = 0;
    for (int fl = 0; fl < 8; fl++) {
        int fg = F0 + fl;
        ULL Ls02 = dup2(__ldg(&Ls[fg * 64 + tx]));
        ULL Ls12 = dup2(__ldg(&Ls[fg * 64 + 32 + tx]));
        ULL Lv02 = dup2(__ldg(&Lv[fg * 32 + tx]));

        if (fl == 0) __syncthreads();   // node arrays ready

        // lin parts
#pragma unroll
        for (int P = 0; P < 4; P++) {
            int nn = nA + 2 * P;
            ULL ag = *(const ULL*)&sAgS[fl * 66 + nn];
            fma2(acc0[P], ag, Ls02);
            fma2(acc1[P], ag, Ls12);
            fma2(acc2[P], *(const ULL*)&sAgV[fl * 66 + nn], Lv02);
            fma2(acc3[P], *(const ULL*)&sAgV[(8 + fl) * 66 + nn], Lv02);
            fma2(acc4[P], *(const ULL*)&sAgV[(16 + fl) * 66 + nn], Lv02);
        }

        // a-first accumulators (per node-pair, per lane output)
        ULL E0[4] = {0,0,0,0}, E1[4] = {0,0,0,0}, Dd[4] = {0,0,0,0};

#pragma unroll 1
        for (int q = 0; q < 4; q++, qi++) {
            if (qi + 2 < 32) node_issue_stage(sW, Wd, qi + 2, tid);
            CP_COMMIT;
            asm volatile("cp.async.wait_group 2;");
            __syncthreads();

            const float* sWq = sW + (qi & 3) * 3072;
#pragma unroll 4
            for (int aa = 0; aa < 16; aa++) {
                int ag_ = q * 16 + aa;
                ULL W02  = *(const ULL*)&sWq[aa * 192 + tx * 2];
                ULL W12  = *(const ULL*)&sWq[aa * 192 + 64 + tx * 2];
                ULL Wv02 = *(const ULL*)&sWq[aa * 192 + 128 + tx * 2];
                ulonglong2 atA = *(const ulonglong2*)&sAtT[ag_ * 68 + nA];
                ulonglong2 atB = *(const ulonglong2*)&sAtT[ag_ * 68 + nA + 4];
                fma2(E0[0], atA.x, W02); fma2(E1[0], atA.x, W12); fma2(Dd[0], atA.x, Wv02);
                fma2(E0[1], atA.y, W02); fma2(E1[1], atA.y, W12); fma2(Dd[1], atA.y, Wv02);
                fma2(E0[2], atB.x, W02); fma2(E1[2], atB.x, W12); fma2(Dd[2], atB.x, Wv02);
                fma2(E0[3], atB.y, W02); fma2(E1[3], atB.y, W12); fma2(Dd[3], atB.y, Wv02);
            }
        }

        // per-f epilogue: multiply by s_f and v_{c,f}
#pragma unroll
        for (int P = 0; P < 4; P++) {
            int nn = nA + 2 * P;
            ULL sf2 = *(const ULL*)&sST[fl * 66 + nn];
            fma2(acc0[P], sf2, E0[P]);
            fma2(acc1[P], sf2, E1[P]);
            fma2(acc2[P], *(const ULL*)&sVT[fl * 66 + nn], Dd[P]);
            fma2(acc3[P], *(const ULL*)&sVT[(8 + fl) * 66 + nn], Dd[P]);
            fma2(acc4[P], *(const ULL*)&sVT[(16 + fl) * 66 + nn], Dd[P]);
        }
    }

    // epilogue: RED partial sums into g_pre
#pragma unroll
    for (int P = 0; P < 4; P++) {
        float ft[2], gt[2], a2[2], a3[2], a4[2];
        upk2(acc0[P], ft[0], ft[1]);
        upk2(acc1[P], gt[0], gt[1]);
        upk2(acc2[P], a2[0], a2[1]);
        upk2(acc3[P], a3[0], a3[1]);
        upk2(acc4[P], a4[0], a4[1]);
#pragma unroll
        for (int h = 0; h < 2; h++) {
            int gn = base + nA + 2 * P + h;
            if (gn < NN) {
                float* p = g_pre + (long)gn * 160 + tx;
                atomicAdd(p, ft[h]);
                atomicAdd(p + 32, gt[h]);
                atomicAdd(p + 64, a2[h]);
                atomicAdd(p + 96, a3[h]);
                atomicAdd(p + 128, a4[h]);
            }
        }
    }
}

// ---------------- node epilogue ---------------------------------------------
__global__ void epi_kernel() {
    int idx = blockIdx.x * 256 + threadIdx.x;
    if (idx >= NN * 32) return;
    int n = idx >> 5, tx = idx & 31;
    const float* p = g_pre + (long)n * 160 + tx;
    float ft = p[0], gt = p[32], a2 = p[64], a3 = p[96], a4 = p[128];
    float4 o = ((float4*)g_sv)[idx];
    float sg = fsig(gt);
    float s_new = fsilu(ft) + o.x;
    ((float4*)g_sv)[idx] =
        make_float4(s_new, a2 * sg + o.y, a3 * sg + o.z, a4 * sg + o.w);
}

// ---------------- output assembly -------------------------------------------
__global__ void out_kernel(float* __restrict__ out) {
    int idx = blockIdx.x * 256 + threadIdx.x;
    if (idx >= NN * 128) return;
    int n = idx >> 7, j = idx & 127;
    float val;
    if (j < 32) {
        val = g_sv[((long)n * 32 + j) * 4];
    } else {
        int t = j - 32;
        int f = t / 3;
        int c = t - 3 * f;
        val = g_sv[((long)n * 32 + f) * 4 + 1 + c];
    }
    out[idx] = val;
}

// ---------------- launch -----------------------------------------------------
extern "C" void kernel_launch(void* const* d_in, const int* in_sizes, int n_in,
                              void* d_out, int out_size) {
    const float* attrs  = (const float*)d_in[0];
    const float* coords = (const float*)d_in[1];
    const int*   eidx   = (const int*)d_in[2];
    const float* embW   = (const float*)d_in[3];
    const float* rW1    = (const float*)d_in[4];
    const float* rb1    = (const float*)d_in[5];
    const float* rW2    = (const float*)d_in[6];
    const float* Ls     = (const float*)d_in[7];
    const float* Lv     = (const float*)d_in[8];
    const float* Ws     = (const float*)d_in[9];
    const float* Wv     = (const float*)d_in[10];
    float* out = (float*)d_out;

    cudaFuncSetAttribute(node_kernel,
                         cudaFuncAttributeMaxDynamicSharedMemorySize,
                         NODE_SMEM_BYTES);

    void *pagg = nullptr, *ppre = nullptr, *pwd = nullptr, *ptab2 = nullptr;
    cudaGetSymbolAddress(&pagg, g_agg);
    cudaGetSymbolAddress(&ppre, g_pre);
    cudaGetSymbolAddress(&pwd, g_wdup);
    cudaGetSymbolAddress(&ptab2, g_tab2);

    tab_kernel<<<2 * TT, 160>>>(rW1, rb1, rW2);
    pair_kernel<<<(2 * TT * 160 + 255) / 256, 256>>>();
    dupw_kernel<<<3072, 256>>>(Ws, Wv);
    geom_kernel<<<(EE + 255) / 256, 256>>>(coords, eidx);
    emb_kernel<<<NN * 32 / 256, 256>>>(attrs, embW);

    for (int l = 0; l < 2; l++) {
        cudaMemsetAsync(pagg, 0, NN * 128 * sizeof(float));
        cudaMemsetAsync(ppre, 0, NN * 160 * sizeof(float));
        edge_kernel<<<1184, 256>>>((const float2*)ptab2 + (long)l * TT * 160);
        node_kernel<<<NTILES * 4, 256, NODE_SMEM_BYTES>>>(
            attrs, Ls + l * 2048, Lv + l * 1024,
            (const float*)pwd + (long)l * 393216);
        epi_kernel<<<(NN * 32 + 255) / 256, 256>>>();
    }
    out_kernel<<<(NN * 128 + 255) / 256, 256>>>(out);
}